// round 13
// baseline (speedup 1.0000x reference)
#include <cuda_runtime.h>

typedef unsigned long long ull;

// ---------------- static device scratch (no allocations allowed) ----------------
__device__ float g_y[2048 * 384];           // conv outputs + bias, rows r = l*32+b
__device__ float g_h[2048 * 384];           // post-BN/leaky/mask features
__device__ float g_mean[384];
__device__ float g_rstd[384];
__device__ float g_a[32 * 64 * 128];        // (b,l,128): h @ w0[:C] + b0
__device__ float g_bb[32 * 64 * 128];       // (b,l,128): h @ w0[C:]
__device__ float g_pacc[4 * 2048 * 128];    // per-j-chunk partial sums
__device__ float g_q[2048 * 128];           // output-MLP hidden

__device__ __forceinline__ float lk(float x) { return x >= 0.f ? x : 0.1f * x; }

__device__ __forceinline__ void fma2(ull& acc, ull a, ull b) {
    asm("fma.rn.f32x2 %0,%1,%2,%0;" : "+l"(acc) : "l"(a), "l"(b));
}
__device__ __forceinline__ ull pack2(float x) {
    ull r; asm("mov.b64 %0,{%1,%1};" : "=l"(r) : "f"(x)); return r;
}
__device__ __forceinline__ float2 unpk(ull v) {
    float2 f; asm("mov.b64 {%0,%1},%2;" : "=f"(f.x), "=f"(f.y) : "l"(v)); return f;
}

// =====================================================================
// Kernel 1: both convolutions as shifted GEMMs (merged grid)
// GEMM: M=2048 (r=l*32+b), N=COUT, K=WIN*512; tile 64m x 32n, BK=32
// 256 threads, per-thread 4m x 2n via f32x2
// =====================================================================
template <int WIN>
__device__ __forceinline__ void conv_gemm(const float* __restrict__ x,
                                          const float* __restrict__ mask,
                                          const float* __restrict__ w,
                                          const float* __restrict__ bias,
                                          int bm0, int bn0, int coff,
                                          float* As, float* Bs) {
    constexpr int K = WIN * 512;
    const int t = threadIdx.x;
    const int tm = t >> 4, tn = t & 15;
    ull acc[4] = {0ULL, 0ULL, 0ULL, 0ULL};

    for (int k0 = 0; k0 < K; k0 += 32) {
        #pragma unroll
        for (int it = 0; it < 8; ++it) {
            int idx = t + it * 256;                // 0..2047
            int kk = idx & 31, mm = idx >> 5;
            int r = bm0 + mm, l = r >> 5, bq = r & 31;
            int kidx = k0 + kk;
            int e = kidx & 511;
            int lp = l + (kidx >> 9) - (WIN - 1) / 2;
            float v = 0.f;
            if (lp >= 0 && lp < 64) {
                int rb = lp * 32 + bq;
                v = x[rb * 512 + e] * mask[rb];
            }
            As[kk * 65 + mm] = v;
        }
        #pragma unroll
        for (int it = 0; it < 4; ++it) {
            int idx = t + it * 256;                // 0..1023
            int kk = idx & 31, nn = idx >> 5;
            Bs[kk * 34 + nn] = w[(bn0 + nn) * K + k0 + kk];
        }
        __syncthreads();
        #pragma unroll
        for (int kk = 0; kk < 32; ++kk) {
            ull wp = *(const ull*)(Bs + kk * 34 + tn * 2);
            #pragma unroll
            for (int i = 0; i < 4; ++i) {
                ull ap = pack2(As[kk * 65 + tm * 4 + i]);
                fma2(acc[i], ap, wp);
            }
        }
        __syncthreads();
    }
    float blo = bias[bn0 + tn * 2], bhi = bias[bn0 + tn * 2 + 1];
    #pragma unroll
    for (int i = 0; i < 4; ++i) {
        float2 f = unpk(acc[i]);
        int r = bm0 + tm * 4 + i;
        g_y[r * 384 + coff + bn0 + tn * 2]     = f.x + blo;
        g_y[r * 384 + coff + bn0 + tn * 2 + 1] = f.y + bhi;
    }
}

__global__ __launch_bounds__(256) void convs_kernel(const float* __restrict__ x,
                                                    const float* __restrict__ mask,
                                                    const float* __restrict__ cw0,
                                                    const float* __restrict__ cb0,
                                                    const float* __restrict__ cw1,
                                                    const float* __restrict__ cb1) {
    __shared__ float As[32 * 65];
    __shared__ float Bs[32 * 34];
    int bx = blockIdx.x;
    if (bx < 256) {   // conv0: 32 m-tiles x 8 n-tiles (COUT=256)
        conv_gemm<1>(x, mask, cw0, cb0, (bx >> 3) * 64, (bx & 7) * 32, 0, As, Bs);
    } else {          // conv1: 32 m-tiles x 4 n-tiles (COUT=128)
        int b2 = bx - 256;
        conv_gemm<3>(x, mask, cw1, cb1, (b2 >> 2) * 64, (b2 & 3) * 32, 256, As, Bs);
    }
}

// =====================================================================
// Kernel 2: per-channel batch stats (mean, biased var -> rstd)
// =====================================================================
__global__ __launch_bounds__(256) void stats_kernel() {
    const int c = blockIdx.x;
    const int t = threadIdx.x;
    float s = 0.f, s2 = 0.f;
    for (int r = t; r < 2048; r += 256) {
        float v = g_y[r * 384 + c];
        s += v; s2 += v * v;
    }
    __shared__ float ss[256], ss2[256];
    ss[t] = s; ss2[t] = s2;
    __syncthreads();
    for (int off = 128; off > 0; off >>= 1) {
        if (t < off) { ss[t] += ss[t + off]; ss2[t] += ss2[t + off]; }
        __syncthreads();
    }
    if (t == 0) {
        float m = ss[0] * (1.f / 2048.f);
        float var = ss2[0] * (1.f / 2048.f) - m * m;
        g_mean[c] = m;
        g_rstd[c] = rsqrtf(var + 1e-5f);
    }
}

// =====================================================================
// Kernel 3: BN apply + leaky + mask -> h
// =====================================================================
__global__ __launch_bounds__(256) void bn_kernel(const float* __restrict__ mask,
                                                 const float* __restrict__ gamma0,
                                                 const float* __restrict__ beta0,
                                                 const float* __restrict__ gamma1,
                                                 const float* __restrict__ beta1) {
    int idx = blockIdx.x * 256 + threadIdx.x;
    if (idx >= 2048 * 384) return;
    int r = idx / 384, c = idx - r * 384;
    float g  = (c < 256) ? gamma0[c] : gamma1[c - 256];
    float bt = (c < 256) ? beta0[c]  : beta1[c - 256];
    float v = (g_y[idx] - g_mean[c]) * g_rstd[c] * g + bt;
    g_h[idx] = lk(v) * mask[r];
}

// =====================================================================
// Kernel 4: a = h@w0[:C] + b0, bb = h@w0[C:]  (K=384, N=128 each)
// tile 64m x 32n, BK=32; output layout row = b*64 + l
// =====================================================================
__global__ __launch_bounds__(256) void ab_kernel(const float* __restrict__ w0,
                                                 const float* __restrict__ b0) {
    __shared__ float As[32 * 65];
    __shared__ float Bs[32 * 34];
    const int bm0 = blockIdx.x * 64, bn0 = blockIdx.y * 32;
    const int which = blockIdx.z;
    const int t = threadIdx.x, tm = t >> 4, tn = t & 15;
    ull acc[4] = {0ULL, 0ULL, 0ULL, 0ULL};

    for (int k0 = 0; k0 < 384; k0 += 32) {
        #pragma unroll
        for (int it = 0; it < 8; ++it) {
            int idx = t + it * 256;
            int kk = idx & 31, mm = idx >> 5;
            As[kk * 65 + mm] = g_h[(bm0 + mm) * 384 + k0 + kk];
        }
        #pragma unroll
        for (int it = 0; it < 4; ++it) {
            int idx = t + it * 256;
            int nn = idx & 31, kk = idx >> 5;
            Bs[kk * 34 + nn] = w0[(which * 384 + k0 + kk) * 128 + bn0 + nn];
        }
        __syncthreads();
        #pragma unroll
        for (int kk = 0; kk < 32; ++kk) {
            ull wp = *(const ull*)(Bs + kk * 34 + tn * 2);
            #pragma unroll
            for (int i = 0; i < 4; ++i) {
                ull ap = pack2(As[kk * 65 + tm * 4 + i]);
                fma2(acc[i], ap, wp);
            }
        }
        __syncthreads();
    }
    int c = bn0 + tn * 2;
    float blo = 0.f, bhi = 0.f;
    if (which == 0) { blo = b0[c]; bhi = b0[c + 1]; }   // fold b0 into a
    float* dst = which ? g_bb : g_a;
    #pragma unroll
    for (int i = 0; i < 4; ++i) {
        float2 f = unpk(acc[i]);
        int r = bm0 + tm * 4 + i;
        int l = r >> 5, bq = r & 31;
        dst[(bq * 64 + l) * 128 + c]     = f.x + blo;
        dst[(bq * 64 + l) * 128 + c + 1] = f.y + bhi;
    }
}

// =====================================================================
// Kernel 5: fused pairwise MLP — k-packed f32x2 (no pack2 MOVs)
// grid (32 b, 4 j-chunks), 256 threads, 229376 B dynamic smem.
// Warp w owns rows 8w..8w+7 end-to-end -> only __syncwarp in j-loop.
// Weights staged k-interleaved: ws[L][k4*512 + n*4 + kk] = wL[(4*k4+kk)*128 + n]
// acc.lo accumulates even-k products, acc.hi odd-k; epilogue adds halves.
// Thread owns cols n_i = lane + 32*i (i=0..3) and rows m0..m0+7.
// =====================================================================
__global__ __launch_bounds__(256, 1) void pair_kernel(const float* __restrict__ w1,
                                                      const float* __restrict__ b1,
                                                      const float* __restrict__ w2,
                                                      const float* __restrict__ b2,
                                                      const float* __restrict__ w3,
                                                      const float* __restrict__ b3) {
    extern __shared__ float sm[];
    float* ws  = sm;                 // 3 x 16384 (k4-interleaved weights)
    float* act = sm + 3 * 16384;     // 64 x 128 row-major activations

    const int t = threadIdx.x;
    const int b = blockIdx.x, jc = blockIdx.y;

    // stage weights k4-interleaved
    for (int i = t; i < 16384; i += 256) {
        int k = i >> 7, n = i & 127;
        int d = (k >> 2) * 512 + n * 4 + (k & 3);
        ws[d]         = w1[i];
        ws[16384 + d] = w2[i];
        ws[32768 + d] = w3[i];
    }
    __syncthreads();

    const int wid = t >> 5, lane = t & 31;
    const int m0 = wid * 8;

    float bias[3][4];
    #pragma unroll
    for (int i = 0; i < 4; ++i) {
        bias[0][i] = b1[lane + 32 * i];
        bias[1][i] = b2[lane + 32 * i];
        bias[2][i] = b3[lane + 32 * i];
    }

    // a rows for this warp at this thread's columns: register-cache (const over j)
    float areg[8][4];
    #pragma unroll
    for (int r = 0; r < 8; ++r)
        #pragma unroll
        for (int i = 0; i < 4; ++i)
            areg[r][i] = g_a[(b * 64 + m0 + r) * 128 + lane + 32 * i];

    float jacc[8][4];
    #pragma unroll
    for (int r = 0; r < 8; ++r)
        #pragma unroll
        for (int i = 0; i < 4; ++i) jacc[r][i] = 0.f;

    for (int jj = 0; jj < 16; ++jj) {
        const int j = jc * 16 + jj;
        float bbv[4];
        #pragma unroll
        for (int i = 0; i < 4; ++i)
            bbv[i] = g_bb[(b * 64 + j) * 128 + lane + 32 * i];

        // fill: act = leaky(a + bb)   (b0 folded into a)
        #pragma unroll
        for (int r = 0; r < 8; ++r)
            #pragma unroll
            for (int i = 0; i < 4; ++i)
                act[(m0 + r) * 128 + lane + 32 * i] = lk(areg[r][i] + bbv[i]);
        __syncwarp();

        #pragma unroll
        for (int L = 0; L < 3; ++L) {
            const float* wl = ws + L * 16384;
            ull acc[8][4];
            #pragma unroll
            for (int r = 0; r < 8; ++r)
                #pragma unroll
                for (int i = 0; i < 4; ++i) acc[r][i] = 0ULL;

            #pragma unroll 2
            for (int k4 = 0; k4 < 32; ++k4) {
                ulonglong2 wv[4];
                #pragma unroll
                for (int i = 0; i < 4; ++i)
                    wv[i] = *(const ulonglong2*)(wl + k4 * 512 + (lane + 32 * i) * 4);
                #pragma unroll
                for (int r = 0; r < 8; ++r) {
                    ulonglong2 av = *(const ulonglong2*)(act + (m0 + r) * 128 + k4 * 4);
                    #pragma unroll
                    for (int i = 0; i < 4; ++i) {
                        fma2(acc[r][i], av.x, wv[i].x);
                        fma2(acc[r][i], av.y, wv[i].y);
                    }
                }
            }
            __syncwarp();   // all lanes done reading act before overwrite

            #pragma unroll
            for (int r = 0; r < 8; ++r) {
                #pragma unroll
                for (int i = 0; i < 4; ++i) {
                    float2 f = unpk(acc[r][i]);
                    float v = lk(f.x + f.y + bias[L][i]);
                    if (L < 2) act[(m0 + r) * 128 + lane + 32 * i] = v;
                    else       jacc[r][i] += v;
                }
            }
            if (L < 2) __syncwarp();  // writes visible before next layer reads
        }
    }

    #pragma unroll
    for (int r = 0; r < 8; ++r)
        #pragma unroll
        for (int i = 0; i < 4; ++i)
            g_pacc[(jc * 2048 + b * 64 + m0 + r) * 128 + lane + 32 * i] = jacc[r][i];
}

// =====================================================================
// Kernel 6: q = leaky( (mean_j p * mask_i) @ w4 + b4 )
// grid 32 (one b each), 98304 B dynamic smem
// =====================================================================
__global__ __launch_bounds__(256, 1) void qa_kernel(const float* __restrict__ mask,
                                                    const float* __restrict__ w4,
                                                    const float* __restrict__ b4) {
    extern __shared__ float sm[];
    float* ws  = sm;            // 128 x 128
    float* act = sm + 16384;    // 64 x 128
    const int t = threadIdx.x, b = blockIdx.x;

    for (int i = t; i < 4096; i += 256) ((float4*)ws)[i] = ((const float4*)w4)[i];
    __syncthreads();

    const int wid = t >> 5, lane = t & 31;
    const int m0 = wid * 8, col = lane * 4;
    float4 bias = *(const float4*)(b4 + col);

    #pragma unroll
    for (int r = 0; r < 8; ++r) {
        int i = m0 + r;
        int row = b * 64 + i;
        float mk = mask[i * 32 + b] * (1.f / 64.f);
        float4 s = make_float4(0.f, 0.f, 0.f, 0.f);
        #pragma unroll
        for (int cp = 0; cp < 4; ++cp) {
            float4 p = *(const float4*)(g_pacc + (cp * 2048 + row) * 128 + col);
            s.x += p.x; s.y += p.y; s.z += p.z; s.w += p.w;
        }
        s.x *= mk; s.y *= mk; s.z *= mk; s.w *= mk;
        *(float4*)(act + i * 128 + col) = s;
    }
    __syncwarp();

    ull acc0[8], acc1[8];
    #pragma unroll
    for (int r = 0; r < 8; ++r) { acc0[r] = 0ULL; acc1[r] = 0ULL; }
    #pragma unroll 4
    for (int k = 0; k < 128; k += 4) {
        ulonglong2 wk0 = *(const ulonglong2*)(ws + (k + 0) * 128 + col);
        ulonglong2 wk1 = *(const ulonglong2*)(ws + (k + 1) * 128 + col);
        ulonglong2 wk2 = *(const ulonglong2*)(ws + (k + 2) * 128 + col);
        ulonglong2 wk3 = *(const ulonglong2*)(ws + (k + 3) * 128 + col);
        #pragma unroll
        for (int r = 0; r < 8; ++r) {
            float4 av = *(const float4*)(act + (m0 + r) * 128 + k);
            ull p0 = pack2(av.x), p1 = pack2(av.y), p2 = pack2(av.z), p3 = pack2(av.w);
            fma2(acc0[r], p0, wk0.x); fma2(acc1[r], p0, wk0.y);
            fma2(acc0[r], p1, wk1.x); fma2(acc1[r], p1, wk1.y);
            fma2(acc0[r], p2, wk2.x); fma2(acc1[r], p2, wk2.y);
            fma2(acc0[r], p3, wk3.x); fma2(acc1[r], p3, wk3.y);
        }
    }
    #pragma unroll
    for (int r = 0; r < 8; ++r) {
        float2 lo = unpk(acc0[r]);
        float2 hi = unpk(acc1[r]);
        float4 v;
        v.x = lk(lo.x + bias.x);
        v.y = lk(lo.y + bias.y);
        v.z = lk(hi.x + bias.z);
        v.w = lk(hi.y + bias.w);
        *(float4*)(g_q + (b * 64 + m0 + r) * 128 + col) = v;
    }
}

// =====================================================================
// Kernel 7: out = leaky(q @ w5 + b5) * mask   (128 -> 512, tiled over n)
// grid (32 b, 4 n-tiles), 98304 B dynamic smem
// =====================================================================
__global__ __launch_bounds__(256, 1) void outb_kernel(const float* __restrict__ mask,
                                                      const float* __restrict__ w5,
                                                      const float* __restrict__ b5,
                                                      float* __restrict__ out) {
    extern __shared__ float sm[];
    float* ws  = sm;            // 128 x 128 slice of w5
    float* act = sm + 16384;    // 64 x 128
    const int t = threadIdx.x, b = blockIdx.x;
    const int n0 = blockIdx.y * 128;

    for (int i = t; i < 4096; i += 256) {
        int k = i >> 5, nq = i & 31;
        ((float4*)ws)[k * 32 + nq] = ((const float4*)(w5 + k * 512 + n0))[nq];
    }
    __syncthreads();

    const int wid = t >> 5, lane = t & 31;
    const int m0 = wid * 8, col = lane * 4;
    float4 bias = *(const float4*)(b5 + n0 + col);

    #pragma unroll
    for (int r = 0; r < 8; ++r) {
        int row = b * 64 + m0 + r;
        *(float4*)(act + (m0 + r) * 128 + col) = *(const float4*)(g_q + row * 128 + col);
    }
    __syncwarp();

    ull acc0[8], acc1[8];
    #pragma unroll
    for (int r = 0; r < 8; ++r) { acc0[r] = 0ULL; acc1[r] = 0ULL; }
    #pragma unroll 4
    for (int k = 0; k < 128; k += 4) {
        ulonglong2 wk0 = *(const ulonglong2*)(ws + (k + 0) * 128 + col);
        ulonglong2 wk1 = *(const ulonglong2*)(ws + (k + 1) * 128 + col);
        ulonglong2 wk2 = *(const ulonglong2*)(ws + (k + 2) * 128 + col);
        ulonglong2 wk3 = *(const ulonglong2*)(ws + (k + 3) * 128 + col);
        #pragma unroll
        for (int r = 0; r < 8; ++r) {
            float4 av = *(const float4*)(act + (m0 + r) * 128 + k);
            ull p0 = pack2(av.x), p1 = pack2(av.y), p2 = pack2(av.z), p3 = pack2(av.w);
            fma2(acc0[r], p0, wk0.x); fma2(acc1[r], p0, wk0.y);
            fma2(acc0[r], p1, wk1.x); fma2(acc1[r], p1, wk1.y);
            fma2(acc0[r], p2, wk2.x); fma2(acc1[r], p2, wk2.y);
            fma2(acc0[r], p3, wk3.x); fma2(acc1[r], p3, wk3.y);
        }
    }
    #pragma unroll
    for (int r = 0; r < 8; ++r) {
        int i = m0 + r;
        float mk = mask[i * 32 + b];
        float2 lo = unpk(acc0[r]);
        float2 hi = unpk(acc1[r]);
        float4 v;
        v.x = lk(lo.x + bias.x) * mk;
        v.y = lk(lo.y + bias.y) * mk;
        v.z = lk(hi.x + bias.z) * mk;
        v.w = lk(hi.y + bias.w) * mk;
        *(float4*)(out + (i * 32 + b) * 512 + n0 + col) = v;
    }
}

// =====================================================================
extern "C" void kernel_launch(void* const* d_in, const int* in_sizes, int n_in,
                              void* d_out, int out_size) {
    const float* x     = (const float*)d_in[0];
    const float* xmask = (const float*)d_in[1];
    const float* cw0   = (const float*)d_in[2];
    const float* cb0   = (const float*)d_in[3];
    const float* gam0  = (const float*)d_in[4];
    const float* bet0  = (const float*)d_in[5];
    const float* cw1   = (const float*)d_in[6];
    const float* cb1   = (const float*)d_in[7];
    const float* gam1  = (const float*)d_in[8];
    const float* bet1  = (const float*)d_in[9];
    const float* w0    = (const float*)d_in[10];
    const float* b0    = (const float*)d_in[11];
    const float* w1    = (const float*)d_in[12];
    const float* b1    = (const float*)d_in[13];
    const float* w2    = (const float*)d_in[14];
    const float* b2    = (const float*)d_in[15];
    const float* w3    = (const float*)d_in[16];
    const float* b3    = (const float*)d_in[17];
    const float* w4    = (const float*)d_in[18];
    const float* b4    = (const float*)d_in[19];
    const float* w5    = (const float*)d_in[20];
    const float* b5    = (const float*)d_in[21];
    float* out = (float*)d_out;

    cudaFuncSetAttribute(pair_kernel, cudaFuncAttributeMaxDynamicSharedMemorySize, 229376);
    cudaFuncSetAttribute(qa_kernel,   cudaFuncAttributeMaxDynamicSharedMemorySize, 98304);
    cudaFuncSetAttribute(outb_kernel, cudaFuncAttributeMaxDynamicSharedMemorySize, 98304);

    convs_kernel<<<384, 256>>>(x, xmask, cw0, cb0, cw1, cb1);
    stats_kernel<<<384, 256>>>();
    bn_kernel<<<(2048 * 384 + 255) / 256, 256>>>(xmask, gam0, bet0, gam1, bet1);
    ab_kernel<<<dim3(32, 4, 2), 256>>>(w0, b0);
    pair_kernel<<<dim3(32, 4), 256, 229376>>>(w1, b1, w2, b2, w3, b3);
    qa_kernel<<<32, 256, 98304>>>(xmask, w4, b4);
    outb_kernel<<<dim3(32, 4), 256, 98304>>>(xmask, w5, b5, out);
}

// round 14
// speedup vs baseline: 1.0892x; 1.0892x over previous
#include <cuda_runtime.h>
#include <cstdint>

typedef unsigned long long ull;

// ---------------- static device scratch (no allocations allowed) ----------------
__device__ float g_y[2048 * 384];           // conv outputs + bias, rows r = l*32+b
__device__ float g_h[2048 * 384];           // post-BN/leaky/mask features
__device__ float g_mean[384];
__device__ float g_rstd[384];
__device__ float g_a[32 * 64 * 128];        // (b,l,128): h @ w0[:C] + b0
__device__ float g_bb[32 * 64 * 128];       // (b,l,128): h @ w0[C:]
__device__ float g_pacc[4 * 2048 * 128];    // per-j-chunk partial sums
__device__ float g_q[2048 * 128];           // output-MLP hidden

__device__ __forceinline__ float lk(float x) { return x >= 0.f ? x : 0.1f * x; }

__device__ __forceinline__ void fma2(ull& acc, ull a, ull b) {
    asm("fma.rn.f32x2 %0,%1,%2,%0;" : "+l"(acc) : "l"(a), "l"(b));
}
__device__ __forceinline__ ull pack2(float x) {
    ull r; asm("mov.b64 %0,{%1,%1};" : "=l"(r) : "f"(x)); return r;
}
__device__ __forceinline__ float2 unpk(ull v) {
    float2 f; asm("mov.b64 {%0,%1},%2;" : "=f"(f.x), "=f"(f.y) : "l"(v)); return f;
}
__device__ __forceinline__ uint32_t f2tf(float f) {
    uint32_t u; asm("cvt.rna.tf32.f32 %0, %1;" : "=r"(u) : "f"(f)); return u;
}
__device__ __forceinline__ void mma8(float* d,
                                     uint32_t a0, uint32_t a1, uint32_t a2, uint32_t a3,
                                     uint32_t b0, uint32_t b1) {
    asm("mma.sync.aligned.m16n8k8.row.col.f32.tf32.tf32.f32 "
        "{%0,%1,%2,%3}, {%4,%5,%6,%7}, {%8,%9}, {%0,%1,%2,%3};"
        : "+f"(d[0]), "+f"(d[1]), "+f"(d[2]), "+f"(d[3])
        : "r"(a0), "r"(a1), "r"(a2), "r"(a3), "r"(b0), "r"(b1));
}

// =====================================================================
// Kernel 1: both convolutions as shifted GEMMs (merged grid)
// =====================================================================
template <int WIN>
__device__ __forceinline__ void conv_gemm(const float* __restrict__ x,
                                          const float* __restrict__ mask,
                                          const float* __restrict__ w,
                                          const float* __restrict__ bias,
                                          int bm0, int bn0, int coff,
                                          float* As, float* Bs) {
    constexpr int K = WIN * 512;
    const int t = threadIdx.x;
    const int tm = t >> 4, tn = t & 15;
    ull acc[4] = {0ULL, 0ULL, 0ULL, 0ULL};

    for (int k0 = 0; k0 < K; k0 += 32) {
        #pragma unroll
        for (int it = 0; it < 8; ++it) {
            int idx = t + it * 256;                // 0..2047
            int kk = idx & 31, mm = idx >> 5;
            int r = bm0 + mm, l = r >> 5, bq = r & 31;
            int kidx = k0 + kk;
            int e = kidx & 511;
            int lp = l + (kidx >> 9) - (WIN - 1) / 2;
            float v = 0.f;
            if (lp >= 0 && lp < 64) {
                int rb = lp * 32 + bq;
                v = x[rb * 512 + e] * mask[rb];
            }
            As[kk * 65 + mm] = v;
        }
        #pragma unroll
        for (int it = 0; it < 4; ++it) {
            int idx = t + it * 256;                // 0..1023
            int kk = idx & 31, nn = idx >> 5;
            Bs[kk * 34 + nn] = w[(bn0 + nn) * K + k0 + kk];
        }
        __syncthreads();
        #pragma unroll
        for (int kk = 0; kk < 32; ++kk) {
            ull wp = *(const ull*)(Bs + kk * 34 + tn * 2);
            #pragma unroll
            for (int i = 0; i < 4; ++i) {
                ull ap = pack2(As[kk * 65 + tm * 4 + i]);
                fma2(acc[i], ap, wp);
            }
        }
        __syncthreads();
    }
    float blo = bias[bn0 + tn * 2], bhi = bias[bn0 + tn * 2 + 1];
    #pragma unroll
    for (int i = 0; i < 4; ++i) {
        float2 f = unpk(acc[i]);
        int r = bm0 + tm * 4 + i;
        g_y[r * 384 + coff + bn0 + tn * 2]     = f.x + blo;
        g_y[r * 384 + coff + bn0 + tn * 2 + 1] = f.y + bhi;
    }
}

__global__ __launch_bounds__(256) void convs_kernel(const float* __restrict__ x,
                                                    const float* __restrict__ mask,
                                                    const float* __restrict__ cw0,
                                                    const float* __restrict__ cb0,
                                                    const float* __restrict__ cw1,
                                                    const float* __restrict__ cb1) {
    __shared__ float As[32 * 65];
    __shared__ float Bs[32 * 34];
    int bx = blockIdx.x;
    if (bx < 256) {   // conv0: 32 m-tiles x 8 n-tiles (COUT=256)
        conv_gemm<1>(x, mask, cw0, cb0, (bx >> 3) * 64, (bx & 7) * 32, 0, As, Bs);
    } else {          // conv1: 32 m-tiles x 4 n-tiles (COUT=128)
        int b2 = bx - 256;
        conv_gemm<3>(x, mask, cw1, cb1, (b2 >> 2) * 64, (b2 & 3) * 32, 256, As, Bs);
    }
}

// =====================================================================
// Kernel 2: per-channel batch stats (mean, biased var -> rstd)
// =====================================================================
__global__ __launch_bounds__(256) void stats_kernel() {
    const int c = blockIdx.x;
    const int t = threadIdx.x;
    float s = 0.f, s2 = 0.f;
    for (int r = t; r < 2048; r += 256) {
        float v = g_y[r * 384 + c];
        s += v; s2 += v * v;
    }
    __shared__ float ss[256], ss2[256];
    ss[t] = s; ss2[t] = s2;
    __syncthreads();
    for (int off = 128; off > 0; off >>= 1) {
        if (t < off) { ss[t] += ss[t + off]; ss2[t] += ss2[t + off]; }
        __syncthreads();
    }
    if (t == 0) {
        float m = ss[0] * (1.f / 2048.f);
        float var = ss2[0] * (1.f / 2048.f) - m * m;
        g_mean[c] = m;
        g_rstd[c] = rsqrtf(var + 1e-5f);
    }
}

// =====================================================================
// Kernel 3: BN apply + leaky + mask -> h
// =====================================================================
__global__ __launch_bounds__(256) void bn_kernel(const float* __restrict__ mask,
                                                 const float* __restrict__ gamma0,
                                                 const float* __restrict__ beta0,
                                                 const float* __restrict__ gamma1,
                                                 const float* __restrict__ beta1) {
    int idx = blockIdx.x * 256 + threadIdx.x;
    if (idx >= 2048 * 384) return;
    int r = idx / 384, c = idx - r * 384;
    float g  = (c < 256) ? gamma0[c] : gamma1[c - 256];
    float bt = (c < 256) ? beta0[c]  : beta1[c - 256];
    float v = (g_y[idx] - g_mean[c]) * g_rstd[c] * g + bt;
    g_h[idx] = lk(v) * mask[r];
}

// =====================================================================
// Kernel 4: a = h@w0[:C] + b0, bb = h@w0[C:]  (K=384, N=128 each)
// =====================================================================
__global__ __launch_bounds__(256) void ab_kernel(const float* __restrict__ w0,
                                                 const float* __restrict__ b0) {
    __shared__ float As[32 * 65];
    __shared__ float Bs[32 * 34];
    const int bm0 = blockIdx.x * 64, bn0 = blockIdx.y * 32;
    const int which = blockIdx.z;
    const int t = threadIdx.x, tm = t >> 4, tn = t & 15;
    ull acc[4] = {0ULL, 0ULL, 0ULL, 0ULL};

    for (int k0 = 0; k0 < 384; k0 += 32) {
        #pragma unroll
        for (int it = 0; it < 8; ++it) {
            int idx = t + it * 256;
            int kk = idx & 31, mm = idx >> 5;
            As[kk * 65 + mm] = g_h[(bm0 + mm) * 384 + k0 + kk];
        }
        #pragma unroll
        for (int it = 0; it < 4; ++it) {
            int idx = t + it * 256;
            int nn = idx & 31, kk = idx >> 5;
            Bs[kk * 34 + nn] = w0[(which * 384 + k0 + kk) * 128 + bn0 + nn];
        }
        __syncthreads();
        #pragma unroll
        for (int kk = 0; kk < 32; ++kk) {
            ull wp = *(const ull*)(Bs + kk * 34 + tn * 2);
            #pragma unroll
            for (int i = 0; i < 4; ++i) {
                ull ap = pack2(As[kk * 65 + tm * 4 + i]);
                fma2(acc[i], ap, wp);
            }
        }
        __syncthreads();
    }
    int c = bn0 + tn * 2;
    float blo = 0.f, bhi = 0.f;
    if (which == 0) { blo = b0[c]; bhi = b0[c + 1]; }   // fold b0 into a
    float* dst = which ? g_bb : g_a;
    #pragma unroll
    for (int i = 0; i < 4; ++i) {
        float2 f = unpk(acc[i]);
        int r = bm0 + tm * 4 + i;
        int l = r >> 5, bq = r & 31;
        dst[(bq * 64 + l) * 128 + c]     = f.x + blo;
        dst[(bq * 64 + l) * 128 + c + 1] = f.y + bhi;
    }
}

// =====================================================================
// Kernel 5: fused pairwise MLP on TF32 tensor cores (mma.sync m16n8k8)
// grid (32 b, 4 jc), 256 threads (8 warps, 2x4 row/col bands),
// 229376 B dyn smem: 3 x (128x128) tf32 weights + 64x128 tf32 act,
// both in XOR-swizzled k-pair layout:
//   float index k -> ks=k>>3, tig=k&3, par=(k>>2)&1, chunk=ks*4+tig
//   stored at row*128 + ((chunk ^ (row&7))<<1) + par
// => A frag (a0,a2)/(a1,a3) and B frag (b0,b1) are single LDS.64, no conflicts.
// =====================================================================
__global__ __launch_bounds__(256, 1) void pair_kernel(const float* __restrict__ w1,
                                                      const float* __restrict__ b1,
                                                      const float* __restrict__ w2,
                                                      const float* __restrict__ b2,
                                                      const float* __restrict__ w3,
                                                      const float* __restrict__ b3) {
    extern __shared__ uint32_t smu[];
    uint32_t* ws  = smu;             // 3 * 16384
    uint32_t* act = smu + 49152;     // 64 * 128

    const int t = threadIdx.x;
    const int b = blockIdx.x, jc = blockIdx.y;

    // stage weights (tf32-converted, swizzled). w row-major [k][n].
    for (int i = t; i < 16384; i += 256) {
        int k = i >> 7, n = i & 127;
        int pos = n * 128 + (((((k >> 3) << 2) + (k & 3)) ^ (n & 7)) << 1) + ((k >> 2) & 1);
        ws[pos]         = f2tf(w1[i]);
        ws[16384 + pos] = f2tf(w2[i]);
        ws[32768 + pos] = f2tf(w3[i]);
    }
    __syncthreads();

    const int lane = t & 31, wid = t >> 5;
    const int g = lane >> 2, tig = lane & 3;
    const int mb = (wid >> 2) << 5;     // 0 / 32
    const int nb = (wid & 3) << 5;      // 0 / 32 / 64 / 96
    const int gk = g >> 2;
    const int tigx = (tig ^ (g & 3)) << 1;

    float bias_r[3][8];
    #pragma unroll
    for (int nt = 0; nt < 4; ++nt) {
        int c = nb + nt * 8 + 2 * tig;
        bias_r[0][nt * 2] = b1[c]; bias_r[0][nt * 2 + 1] = b1[c + 1];
        bias_r[1][nt * 2] = b2[c]; bias_r[1][nt * 2 + 1] = b2[c + 1];
        bias_r[2][nt * 2] = b3[c]; bias_r[2][nt * 2 + 1] = b3[c + 1];
    }

    float jacc[8][4];
    #pragma unroll
    for (int q = 0; q < 8; ++q)
        #pragma unroll
        for (int e = 0; e < 4; ++e) jacc[q][e] = 0.f;

    const int arow0 = (mb + g) * 128;
    const int arow1 = (mb + g + 8) * 128;
    const int arow2 = (mb + g + 16) * 128;
    const int arow3 = (mb + g + 24) * 128;

    const int kfill = t & 127;
    const int ifill = t >> 7;
    const int fchunk = ((kfill >> 3) << 2) + (kfill & 3);
    const int fpar = (kfill >> 2) & 1;

    for (int jj = 0; jj < 16; ++jj) {
        const int j = jc * 16 + jj;
        // fill: act = tf32(leaky(a + bb)), swizzled; thread owns column kfill
        float bbv = g_bb[(b * 64 + j) * 128 + kfill];
        #pragma unroll 8
        for (int n = 0; n < 32; ++n) {
            int i = ifill + n * 2;
            float av = g_a[(b * 64 + i) * 128 + kfill];
            act[i * 128 + ((fchunk ^ (i & 7)) << 1) + fpar] = f2tf(lk(av + bbv));
        }
        __syncthreads();

        #pragma unroll
        for (int L = 0; L < 3; ++L) {
            const uint32_t* wl = ws + L * 16384;
            float D[8][4];
            #pragma unroll
            for (int q = 0; q < 8; ++q)
                #pragma unroll
                for (int e = 0; e < 4; ++e) D[q][e] = 0.f;

            #pragma unroll
            for (int ks = 0; ks < 16; ++ks) {
                const int koff = ((ks ^ gk) << 3) + tigx;
                uint2 a00 = *(const uint2*)(act + arow0 + koff);  // mt0: (a0,a2)
                uint2 a01 = *(const uint2*)(act + arow1 + koff);  // mt0: (a1,a3)
                uint2 a10 = *(const uint2*)(act + arow2 + koff);  // mt1
                uint2 a11 = *(const uint2*)(act + arow3 + koff);
                #pragma unroll
                for (int nt = 0; nt < 4; ++nt) {
                    uint2 bf = *(const uint2*)(wl + (nb + nt * 8 + g) * 128 + koff);
                    mma8(D[nt],     a00.x, a01.x, a00.y, a01.y, bf.x, bf.y);
                    mma8(D[4 + nt], a10.x, a11.x, a10.y, a11.y, bf.x, bf.y);
                }
            }
            __syncthreads();   // all reads of act complete

            if (L < 2) {
                #pragma unroll
                for (int mt = 0; mt < 2; ++mt) {
                    #pragma unroll
                    for (int nt = 0; nt < 4; ++nt) {
                        float* f = D[mt * 4 + nt];
                        int c0 = nb + nt * 8 + 2 * tig;           // even
                        int chunk = ((c0 >> 3) << 2) + (c0 & 3);
                        int par = (c0 >> 2) & 1;
                        int r0 = (mb + mt * 16 + g) * 128;
                        int r1 = r0 + 8 * 128;
                        int p0 = ((chunk ^ g) << 1) + par;        // (row&7)==g
                        int p1 = (((chunk + 1) ^ g) << 1) + par;
                        float blo = bias_r[L][nt * 2], bhi = bias_r[L][nt * 2 + 1];
                        act[r0 + p0] = f2tf(lk(f[0] + blo));
                        act[r0 + p1] = f2tf(lk(f[1] + bhi));
                        act[r1 + p0] = f2tf(lk(f[2] + blo));
                        act[r1 + p1] = f2tf(lk(f[3] + bhi));
                    }
                }
                __syncthreads();   // writes visible before next layer reads
            } else {
                #pragma unroll
                for (int q = 0; q < 8; ++q) {
                    float blo = bias_r[2][(q & 3) * 2], bhi = bias_r[2][(q & 3) * 2 + 1];
                    jacc[q][0] += lk(D[q][0] + blo);
                    jacc[q][1] += lk(D[q][1] + bhi);
                    jacc[q][2] += lk(D[q][2] + blo);
                    jacc[q][3] += lk(D[q][3] + bhi);
                }
                // sync from this layer's k-loop already guards next fill
            }
        }
    }

    // write per-jc partial sums (fp32)
    #pragma unroll
    for (int mt = 0; mt < 2; ++mt)
        #pragma unroll
        for (int nt = 0; nt < 4; ++nt) {
            float* f = jacc[mt * 4 + nt];
            int c0 = nb + nt * 8 + 2 * tig;
            int r0 = jc * 2048 + b * 64 + mb + mt * 16 + g;
            *(float2*)(g_pacc + r0 * 128 + c0)       = make_float2(f[0], f[1]);
            *(float2*)(g_pacc + (r0 + 8) * 128 + c0) = make_float2(f[2], f[3]);
        }
}

// =====================================================================
// Kernel 6: q = leaky( (mean_j p * mask_i) @ w4 + b4 )
// =====================================================================
__global__ __launch_bounds__(256, 1) void qa_kernel(const float* __restrict__ mask,
                                                    const float* __restrict__ w4,
                                                    const float* __restrict__ b4) {
    extern __shared__ float sm[];
    float* ws  = sm;            // 128 x 128
    float* act = sm + 16384;    // 64 x 128
    const int t = threadIdx.x, b = blockIdx.x;

    for (int i = t; i < 4096; i += 256) ((float4*)ws)[i] = ((const float4*)w4)[i];
    __syncthreads();

    const int wid = t >> 5, lane = t & 31;
    const int m0 = wid * 8, col = lane * 4;
    float4 bias = *(const float4*)(b4 + col);

    #pragma unroll
    for (int r = 0; r < 8; ++r) {
        int i = m0 + r;
        int row = b * 64 + i;
        float mk = mask[i * 32 + b] * (1.f / 64.f);
        float4 s = make_float4(0.f, 0.f, 0.f, 0.f);
        #pragma unroll
        for (int cp = 0; cp < 4; ++cp) {
            float4 p = *(const float4*)(g_pacc + (cp * 2048 + row) * 128 + col);
            s.x += p.x; s.y += p.y; s.z += p.z; s.w += p.w;
        }
        s.x *= mk; s.y *= mk; s.z *= mk; s.w *= mk;
        *(float4*)(act + i * 128 + col) = s;
    }
    __syncwarp();

    ull acc0[8], acc1[8];
    #pragma unroll
    for (int r = 0; r < 8; ++r) { acc0[r] = 0ULL; acc1[r] = 0ULL; }
    #pragma unroll 4
    for (int k = 0; k < 128; k += 4) {
        ulonglong2 wk0 = *(const ulonglong2*)(ws + (k + 0) * 128 + col);
        ulonglong2 wk1 = *(const ulonglong2*)(ws + (k + 1) * 128 + col);
        ulonglong2 wk2 = *(const ulonglong2*)(ws + (k + 2) * 128 + col);
        ulonglong2 wk3 = *(const ulonglong2*)(ws + (k + 3) * 128 + col);
        #pragma unroll
        for (int r = 0; r < 8; ++r) {
            float4 av = *(const float4*)(act + (m0 + r) * 128 + k);
            ull p0 = pack2(av.x), p1 = pack2(av.y), p2 = pack2(av.z), p3 = pack2(av.w);
            fma2(acc0[r], p0, wk0.x); fma2(acc1[r], p0, wk0.y);
            fma2(acc0[r], p1, wk1.x); fma2(acc1[r], p1, wk1.y);
            fma2(acc0[r], p2, wk2.x); fma2(acc1[r], p2, wk2.y);
            fma2(acc0[r], p3, wk3.x); fma2(acc1[r], p3, wk3.y);
        }
    }
    #pragma unroll
    for (int r = 0; r < 8; ++r) {
        float2 lo = unpk(acc0[r]);
        float2 hi = unpk(acc1[r]);
        float4 v;
        v.x = lk(lo.x + bias.x);
        v.y = lk(lo.y + bias.y);
        v.z = lk(hi.x + bias.z);
        v.w = lk(hi.y + bias.w);
        *(float4*)(g_q + (b * 64 + m0 + r) * 128 + col) = v;
    }
}

// =====================================================================
// Kernel 7: out = leaky(q @ w5 + b5) * mask   (128 -> 512, tiled over n)
// =====================================================================
__global__ __launch_bounds__(256, 1) void outb_kernel(const float* __restrict__ mask,
                                                      const float* __restrict__ w5,
                                                      const float* __restrict__ b5,
                                                      float* __restrict__ out) {
    extern __shared__ float sm[];
    float* ws  = sm;            // 128 x 128 slice of w5
    float* act = sm + 16384;    // 64 x 128
    const int t = threadIdx.x, b = blockIdx.x;
    const int n0 = blockIdx.y * 128;

    for (int i = t; i < 4096; i += 256) {
        int k = i >> 5, nq = i & 31;
        ((float4*)ws)[k * 32 + nq] = ((const float4*)(w5 + k * 512 + n0))[nq];
    }
    __syncthreads();

    const int wid = t >> 5, lane = t & 31;
    const int m0 = wid * 8, col = lane * 4;
    float4 bias = *(const float4*)(b5 + n0 + col);

    #pragma unroll
    for (int r = 0; r < 8; ++r) {
        int row = b * 64 + m0 + r;
        *(float4*)(act + (m0 + r) * 128 + col) = *(const float4*)(g_q + row * 128 + col);
    }
    __syncwarp();

    ull acc0[8], acc1[8];
    #pragma unroll
    for (int r = 0; r < 8; ++r) { acc0[r] = 0ULL; acc1[r] = 0ULL; }
    #pragma unroll 4
    for (int k = 0; k < 128; k += 4) {
        ulonglong2 wk0 = *(const ulonglong2*)(ws + (k + 0) * 128 + col);
        ulonglong2 wk1 = *(const ulonglong2*)(ws + (k + 1) * 128 + col);
        ulonglong2 wk2 = *(const ulonglong2*)(ws + (k + 2) * 128 + col);
        ulonglong2 wk3 = *(const ulonglong2*)(ws + (k + 3) * 128 + col);
        #pragma unroll
        for (int r = 0; r < 8; ++r) {
            float4 av = *(const float4*)(act + (m0 + r) * 128 + k);
            ull p0 = pack2(av.x), p1 = pack2(av.y), p2 = pack2(av.z), p3 = pack2(av.w);
            fma2(acc0[r], p0, wk0.x); fma2(acc1[r], p0, wk0.y);
            fma2(acc0[r], p1, wk1.x); fma2(acc1[r], p1, wk1.y);
            fma2(acc0[r], p2, wk2.x); fma2(acc1[r], p2, wk2.y);
            fma2(acc0[r], p3, wk3.x); fma2(acc1[r], p3, wk3.y);
        }
    }
    #pragma unroll
    for (int r = 0; r < 8; ++r) {
        int i = m0 + r;
        float mk = mask[i * 32 + b];
        float2 lo = unpk(acc0[r]);
        float2 hi = unpk(acc1[r]);
        float4 v;
        v.x = lk(lo.x + bias.x) * mk;
        v.y = lk(lo.y + bias.y) * mk;
        v.z = lk(hi.x + bias.z) * mk;
        v.w = lk(hi.y + bias.w) * mk;
        *(float4*)(out + (i * 32 + b) * 512 + n0 + col) = v;
    }
}

// =====================================================================
extern "C" void kernel_launch(void* const* d_in, const int* in_sizes, int n_in,
                              void* d_out, int out_size) {
    const float* x     = (const float*)d_in[0];
    const float* xmask = (const float*)d_in[1];
    const float* cw0   = (const float*)d_in[2];
    const float* cb0   = (const float*)d_in[3];
    const float* gam0  = (const float*)d_in[4];
    const float* bet0  = (const float*)d_in[5];
    const float* cw1   = (const float*)d_in[6];
    const float* cb1   = (const float*)d_in[7];
    const float* gam1  = (const float*)d_in[8];
    const float* bet1  = (const float*)d_in[9];
    const float* w0    = (const float*)d_in[10];
    const float* b0    = (const float*)d_in[11];
    const float* w1    = (const float*)d_in[12];
    const float* b1    = (const float*)d_in[13];
    const float* w2    = (const float*)d_in[14];
    const float* b2    = (const float*)d_in[15];
    const float* w3    = (const float*)d_in[16];
    const float* b3    = (const float*)d_in[17];
    const float* w4    = (const float*)d_in[18];
    const float* b4    = (const float*)d_in[19];
    const float* w5    = (const float*)d_in[20];
    const float* b5    = (const float*)d_in[21];
    float* out = (float*)d_out;

    cudaFuncSetAttribute(pair_kernel, cudaFuncAttributeMaxDynamicSharedMemorySize, 229376);
    cudaFuncSetAttribute(qa_kernel,   cudaFuncAttributeMaxDynamicSharedMemorySize, 98304);
    cudaFuncSetAttribute(outb_kernel, cudaFuncAttributeMaxDynamicSharedMemorySize, 98304);

    convs_kernel<<<384, 256>>>(x, xmask, cw0, cb0, cw1, cb1);
    stats_kernel<<<384, 256>>>();
    bn_kernel<<<(2048 * 384 + 255) / 256, 256>>>(xmask, gam0, bet0, gam1, bet1);
    ab_kernel<<<dim3(32, 4, 2), 256>>>(w0, b0);
    pair_kernel<<<dim3(32, 4), 256, 229376>>>(w1, b1, w2, b2, w3, b3);
    qa_kernel<<<32, 256, 98304>>>(xmask, w4, b4);
    outb_kernel<<<dim3(32, 4), 256, 98304>>>(xmask, w5, b5, out);
}

// round 16
// speedup vs baseline: 1.9969x; 1.8333x over previous
#include <cuda_runtime.h>
#include <cstdint>

typedef unsigned long long ull;

// ---------------- static device scratch (no allocations allowed) ----------------
__device__ float g_y[2048 * 384];           // conv outputs + bias, rows r = l*32+b
__device__ float g_h[2048 * 384];           // post-BN/leaky/mask features
__device__ float g_mean[384];
__device__ float g_rstd[384];
__device__ float g_a[32 * 64 * 128];        // (b,l,128): h @ w0[:C] + b0
__device__ float g_bb[32 * 64 * 128];       // (b,l,128): h @ w0[C:]
__device__ float g_pacc[4 * 2048 * 128];    // per j-chunk partial sums
__device__ float g_q[2048 * 128];           // output-MLP hidden

__device__ __forceinline__ float lk(float x) { return x >= 0.f ? x : 0.1f * x; }

__device__ __forceinline__ void fma2(ull& acc, ull a, ull b) {
    asm("fma.rn.f32x2 %0,%1,%2,%0;" : "+l"(acc) : "l"(a), "l"(b));
}
__device__ __forceinline__ ull pack2(float x) {
    ull r; asm("mov.b64 %0,{%1,%1};" : "=l"(r) : "f"(x)); return r;
}
__device__ __forceinline__ float2 unpk(ull v) {
    float2 f; asm("mov.b64 {%0,%1},%2;" : "=f"(f.x), "=f"(f.y) : "l"(v)); return f;
}
// pack two fp32 -> f16x2 word, lo = first arg
__device__ __forceinline__ uint32_t pkh(float lo, float hi) {
    uint32_t r; asm("cvt.rn.f16x2.f32 %0, %1, %2;" : "=r"(r) : "f"(hi), "f"(lo)); return r;
}
// m16n8k16 fp16 MMA, fp32 accumulate
__device__ __forceinline__ void mma16(float* d,
                                      uint32_t a0, uint32_t a1, uint32_t a2, uint32_t a3,
                                      uint32_t b0, uint32_t b1) {
    asm("mma.sync.aligned.m16n8k16.row.col.f32.f16.f16.f32 "
        "{%0,%1,%2,%3}, {%4,%5,%6,%7}, {%8,%9}, {%0,%1,%2,%3};"
        : "+f"(d[0]), "+f"(d[1]), "+f"(d[2]), "+f"(d[3])
        : "r"(a0), "r"(a1), "r"(a2), "r"(a3), "r"(b0), "r"(b1));
}

// =====================================================================
// Kernel 1: both convolutions as shifted GEMMs (merged grid)
// =====================================================================
template <int WIN>
__device__ __forceinline__ void conv_gemm(const float* __restrict__ x,
                                          const float* __restrict__ mask,
                                          const float* __restrict__ w,
                                          const float* __restrict__ bias,
                                          int bm0, int bn0, int coff,
                                          float* As, float* Bs) {
    constexpr int K = WIN * 512;
    const int t = threadIdx.x;
    const int tm = t >> 4, tn = t & 15;
    ull acc[4] = {0ULL, 0ULL, 0ULL, 0ULL};

    for (int k0 = 0; k0 < K; k0 += 32) {
        #pragma unroll
        for (int it = 0; it < 8; ++it) {
            int idx = t + it * 256;
            int kk = idx & 31, mm = idx >> 5;
            int r = bm0 + mm, l = r >> 5, bq = r & 31;
            int kidx = k0 + kk;
            int e = kidx & 511;
            int lp = l + (kidx >> 9) - (WIN - 1) / 2;
            float v = 0.f;
            if (lp >= 0 && lp < 64) {
                int rb = lp * 32 + bq;
                v = x[rb * 512 + e] * mask[rb];
            }
            As[kk * 65 + mm] = v;
        }
        #pragma unroll
        for (int it = 0; it < 4; ++it) {
            int idx = t + it * 256;
            int kk = idx & 31, nn = idx >> 5;
            Bs[kk * 34 + nn] = w[(bn0 + nn) * K + k0 + kk];
        }
        __syncthreads();
        #pragma unroll
        for (int kk = 0; kk < 32; ++kk) {
            ull wp = *(const ull*)(Bs + kk * 34 + tn * 2);
            #pragma unroll
            for (int i = 0; i < 4; ++i) {
                ull ap = pack2(As[kk * 65 + tm * 4 + i]);
                fma2(acc[i], ap, wp);
            }
        }
        __syncthreads();
    }
    float blo = bias[bn0 + tn * 2], bhi = bias[bn0 + tn * 2 + 1];
    #pragma unroll
    for (int i = 0; i < 4; ++i) {
        float2 f = unpk(acc[i]);
        int r = bm0 + tm * 4 + i;
        g_y[r * 384 + coff + bn0 + tn * 2]     = f.x + blo;
        g_y[r * 384 + coff + bn0 + tn * 2 + 1] = f.y + bhi;
    }
}

__global__ __launch_bounds__(256) void convs_kernel(const float* __restrict__ x,
                                                    const float* __restrict__ mask,
                                                    const float* __restrict__ cw0,
                                                    const float* __restrict__ cb0,
                                                    const float* __restrict__ cw1,
                                                    const float* __restrict__ cb1) {
    __shared__ float As[32 * 65];
    __shared__ float Bs[32 * 34];
    int bx = blockIdx.x;
    if (bx < 256) {
        conv_gemm<1>(x, mask, cw0, cb0, (bx >> 3) * 64, (bx & 7) * 32, 0, As, Bs);
    } else {
        int b2 = bx - 256;
        conv_gemm<3>(x, mask, cw1, cb1, (b2 >> 2) * 64, (b2 & 3) * 32, 256, As, Bs);
    }
}

// =====================================================================
// Kernel 2: per-channel batch stats
// =====================================================================
__global__ __launch_bounds__(256) void stats_kernel() {
    const int c = blockIdx.x;
    const int t = threadIdx.x;
    float s = 0.f, s2 = 0.f;
    for (int r = t; r < 2048; r += 256) {
        float v = g_y[r * 384 + c];
        s += v; s2 += v * v;
    }
    __shared__ float ss[256], ss2[256];
    ss[t] = s; ss2[t] = s2;
    __syncthreads();
    for (int off = 128; off > 0; off >>= 1) {
        if (t < off) { ss[t] += ss[t + off]; ss2[t] += ss2[t + off]; }
        __syncthreads();
    }
    if (t == 0) {
        float m = ss[0] * (1.f / 2048.f);
        float var = ss2[0] * (1.f / 2048.f) - m * m;
        g_mean[c] = m;
        g_rstd[c] = rsqrtf(var + 1e-5f);
    }
}

// =====================================================================
// Kernel 3: BN apply + leaky + mask -> h
// =====================================================================
__global__ __launch_bounds__(256) void bn_kernel(const float* __restrict__ mask,
                                                 const float* __restrict__ gamma0,
                                                 const float* __restrict__ beta0,
                                                 const float* __restrict__ gamma1,
                                                 const float* __restrict__ beta1) {
    int idx = blockIdx.x * 256 + threadIdx.x;
    if (idx >= 2048 * 384) return;
    int r = idx / 384, c = idx - r * 384;
    float g  = (c < 256) ? gamma0[c] : gamma1[c - 256];
    float bt = (c < 256) ? beta0[c]  : beta1[c - 256];
    float v = (g_y[idx] - g_mean[c]) * g_rstd[c] * g + bt;
    g_h[idx] = lk(v) * mask[r];
}

// =====================================================================
// Kernel 4: a = h@w0[:C] + b0, bb = h@w0[C:]
// =====================================================================
__global__ __launch_bounds__(256) void ab_kernel(const float* __restrict__ w0,
                                                 const float* __restrict__ b0) {
    __shared__ float As[32 * 65];
    __shared__ float Bs[32 * 34];
    const int bm0 = blockIdx.x * 64, bn0 = blockIdx.y * 32;
    const int which = blockIdx.z;
    const int t = threadIdx.x, tm = t >> 4, tn = t & 15;
    ull acc[4] = {0ULL, 0ULL, 0ULL, 0ULL};

    for (int k0 = 0; k0 < 384; k0 += 32) {
        #pragma unroll
        for (int it = 0; it < 8; ++it) {
            int idx = t + it * 256;
            int kk = idx & 31, mm = idx >> 5;
            As[kk * 65 + mm] = g_h[(bm0 + mm) * 384 + k0 + kk];
        }
        #pragma unroll
        for (int it = 0; it < 4; ++it) {
            int idx = t + it * 256;
            int nn = idx & 31, kk = idx >> 5;
            Bs[kk * 34 + nn] = w0[(which * 384 + k0 + kk) * 128 + bn0 + nn];
        }
        __syncthreads();
        #pragma unroll
        for (int kk = 0; kk < 32; ++kk) {
            ull wp = *(const ull*)(Bs + kk * 34 + tn * 2);
            #pragma unroll
            for (int i = 0; i < 4; ++i) {
                ull ap = pack2(As[kk * 65 + tm * 4 + i]);
                fma2(acc[i], ap, wp);
            }
        }
        __syncthreads();
    }
    int c = bn0 + tn * 2;
    float blo = 0.f, bhi = 0.f;
    if (which == 0) { blo = b0[c]; bhi = b0[c + 1]; }
    float* dst = which ? g_bb : g_a;
    #pragma unroll
    for (int i = 0; i < 4; ++i) {
        float2 f = unpk(acc[i]);
        int r = bm0 + tm * 4 + i;
        int l = r >> 5, bq = r & 31;
        dst[(bq * 64 + l) * 128 + c]     = f.x + blo;
        dst[(bq * 64 + l) * 128 + c + 1] = f.y + bhi;
    }
}

// =====================================================================
// Kernel 5: fused pairwise MLP, fp16 mma.sync.m16n8k16 (fp32 accumulate)
// grid (32 b, 4 jc), 256 threads = 8 warps in 2 row-bands x 4 col-bands.
// SMEM (fp16x2 words, rows padded to 72 words = conflict-free LDS.64):
//   word layout within a row: k-pair kp -> s=kp>>3, jj=kp&7,
//   pos = s*8 + ((jj&3)<<1) + (jj>>2)   (k and k+8 halves adjacent)
//   ws  : 3 x 128 x 72 words (wL[n][kp])     = 110592 B
//   a_s : 64 x 130 fp32                      =  33280 B
//   bb_s: 16 x 130 fp32 (whole jc chunk)     =   8320 B
//   bias: 3 x 128 fp32                       =   1536 B
//   act : 64 x 72 words                      =  18432 B   total 172160 B
// =====================================================================
__global__ __launch_bounds__(256, 1) void pair_kernel(const float* __restrict__ w1,
                                                      const float* __restrict__ b1,
                                                      const float* __restrict__ w2,
                                                      const float* __restrict__ b2,
                                                      const float* __restrict__ w3,
                                                      const float* __restrict__ b3) {
    extern __shared__ float sm[];
    uint32_t* ws    = (uint32_t*)sm;          // 27648 words
    float*    a_s   = sm + 27648;             // 8320
    float*    bb_s  = sm + 27648 + 8320;      // 2080
    float*    bias_s= sm + 27648 + 8320 + 2080; // 384
    uint32_t* actw  = (uint32_t*)(sm + 38432);  // 4608 words

    const int t = threadIdx.x;
    const int b = blockIdx.x, jc = blockIdx.y;

    // ---- stage weights as f16x2, swizzled [n][pos(kp)] ----
    for (int idx = t; idx < 8192; idx += 256) {
        int n = idx & 127, kp = idx >> 7;
        int jj = kp & 7;
        int pos = n * 72 + ((kp >> 3) << 3) + ((jj & 3) << 1) + (jj >> 2);
        int s0 = (2 * kp) * 128 + n, s1 = s0 + 128;
        ws[pos]          = pkh(w1[s0], w1[s1]);
        ws[9216 + pos]   = pkh(w2[s0], w2[s1]);
        ws[18432 + pos]  = pkh(w3[s0], w3[s1]);
    }
    // ---- stage a (fp32), bb chunk, biases ----
    for (int idx = t; idx < 8192; idx += 256) {
        int i = idx >> 7, k = idx & 127;
        a_s[i * 130 + k] = g_a[(b * 64 + i) * 128 + k];
    }
    for (int idx = t; idx < 2048; idx += 256) {
        int jj = idx >> 7, k = idx & 127;
        bb_s[jj * 130 + k] = g_bb[(b * 64 + jc * 16 + jj) * 128 + k];
    }
    if (t < 128) {
        bias_s[t]       = b1[t];
        bias_s[128 + t] = b2[t];
        bias_s[256 + t] = b3[t];
    }
    __syncthreads();

    const int lane = t & 31, wid = t >> 5;
    const int g = lane >> 2, tig = lane & 3;
    const int mb = (wid >> 2) << 5;     // 0 / 32
    const int nb = (wid & 3) << 5;      // 0 / 32 / 64 / 96

    // fill-role constants: thread owns k-pair kp_f, row set ih*16..+15
    const int kp_f = t & 63, ih = t >> 6;
    const int jjf = kp_f & 7;
    const int pos_f = ((kp_f >> 3) << 3) + ((jjf & 3) << 1) + (jjf >> 2);

    // epilogue positions per n-tile (c0 = nb + nt*8 + 2*tig)
    int epos[4];
    #pragma unroll
    for (int nt = 0; nt < 4; ++nt) {
        int kp = (nb >> 1) + nt * 4 + tig;
        int jj = kp & 7;
        epos[nt] = ((kp >> 3) << 3) + ((jj & 3) << 1) + (jj >> 2);
    }

    float jacc[8][4];
    #pragma unroll
    for (int q = 0; q < 8; ++q)
        #pragma unroll
        for (int e = 0; e < 4; ++e) jacc[q][e] = 0.f;

    for (int jj16 = 0; jj16 < 16; ++jj16) {
        // ---- fill: act = f16(leaky(a + bb)) ----
        {
            float2 bv = *(const float2*)(bb_s + jj16 * 130 + 2 * kp_f);
            #pragma unroll
            for (int q = 0; q < 16; ++q) {
                int i = ih * 16 + q;
                float2 av = *(const float2*)(a_s + i * 130 + 2 * kp_f);
                actw[i * 72 + pos_f] = pkh(lk(av.x + bv.x), lk(av.y + bv.y));
            }
        }
        __syncthreads();

        #pragma unroll
        for (int L = 0; L < 3; ++L) {
            const uint32_t* wl = ws + L * 9216;
            float D[8][4];
            #pragma unroll
            for (int q = 0; q < 8; ++q)
                #pragma unroll
                for (int e = 0; e < 4; ++e) D[q][e] = 0.f;

            #pragma unroll
            for (int s = 0; s < 8; ++s) {
                const int ko = s * 8 + tig * 2;
                uint2 aA = *(const uint2*)(actw + (mb + g) * 72 + ko);
                uint2 aB = *(const uint2*)(actw + (mb + g + 8) * 72 + ko);
                uint2 aC = *(const uint2*)(actw + (mb + g + 16) * 72 + ko);
                uint2 aD = *(const uint2*)(actw + (mb + g + 24) * 72 + ko);
                #pragma unroll
                for (int nt = 0; nt < 4; ++nt) {
                    uint2 bw = *(const uint2*)(wl + (nb + nt * 8 + g) * 72 + ko);
                    mma16(D[nt],     aA.x, aB.x, aA.y, aB.y, bw.x, bw.y);
                    mma16(D[4 + nt], aC.x, aD.x, aC.y, aD.y, bw.x, bw.y);
                }
            }
            __syncthreads();   // all act reads complete

            if (L < 2) {
                #pragma unroll
                for (int mt = 0; mt < 2; ++mt) {
                    #pragma unroll
                    for (int nt = 0; nt < 4; ++nt) {
                        float* f = D[mt * 4 + nt];
                        int c0 = nb + nt * 8 + 2 * tig;
                        float2 bi = *(const float2*)(bias_s + L * 128 + c0);
                        int r0 = (mb + mt * 16 + g) * 72;
                        actw[r0 + epos[nt]]            = pkh(lk(f[0] + bi.x), lk(f[1] + bi.y));
                        actw[r0 + 8 * 72 + epos[nt]]   = pkh(lk(f[2] + bi.x), lk(f[3] + bi.y));
                    }
                }
                __syncthreads();   // writes visible before next layer reads
            } else {
                #pragma unroll
                for (int mt = 0; mt < 2; ++mt)
                    #pragma unroll
                    for (int nt = 0; nt < 4; ++nt) {
                        float* f = D[mt * 4 + nt];
                        int c0 = nb + nt * 8 + 2 * tig;
                        float2 bi = *(const float2*)(bias_s + 256 + c0);
                        float* ja = jacc[mt * 4 + nt];
                        ja[0] += lk(f[0] + bi.x);
                        ja[1] += lk(f[1] + bi.y);
                        ja[2] += lk(f[2] + bi.x);
                        ja[3] += lk(f[3] + bi.y);
                    }
            }
        }
    }

    // ---- write per-jc partials ----
    #pragma unroll
    for (int mt = 0; mt < 2; ++mt)
        #pragma unroll
        for (int nt = 0; nt < 4; ++nt) {
            float* f = jacc[mt * 4 + nt];
            int c0 = nb + nt * 8 + 2 * tig;
            int r0 = jc * 2048 + b * 64 + mb + mt * 16 + g;
            *(float2*)(g_pacc + r0 * 128 + c0)       = make_float2(f[0], f[1]);
            *(float2*)(g_pacc + (r0 + 8) * 128 + c0) = make_float2(f[2], f[3]);
        }
}

// =====================================================================
// Kernel 6: q = leaky( (mean_j p * mask_i) @ w4 + b4 )
// =====================================================================
__global__ __launch_bounds__(256, 1) void qa_kernel(const float* __restrict__ mask,
                                                    const float* __restrict__ w4,
                                                    const float* __restrict__ b4) {
    extern __shared__ float sm[];
    float* ws  = sm;            // 128 x 128
    float* act = sm + 16384;    // 64 x 128
    const int t = threadIdx.x, b = blockIdx.x;

    for (int i = t; i < 4096; i += 256) ((float4*)ws)[i] = ((const float4*)w4)[i];
    __syncthreads();

    const int wid = t >> 5, lane = t & 31;
    const int m0 = wid * 8, col = lane * 4;
    float4 bias = *(const float4*)(b4 + col);

    #pragma unroll
    for (int r = 0; r < 8; ++r) {
        int i = m0 + r;
        int row = b * 64 + i;
        float mk = mask[i * 32 + b] * (1.f / 64.f);
        float4 s = make_float4(0.f, 0.f, 0.f, 0.f);
        #pragma unroll
        for (int cp = 0; cp < 4; ++cp) {
            float4 p = *(const float4*)(g_pacc + (cp * 2048 + row) * 128 + col);
            s.x += p.x; s.y += p.y; s.z += p.z; s.w += p.w;
        }
        s.x *= mk; s.y *= mk; s.z *= mk; s.w *= mk;
        *(float4*)(act + i * 128 + col) = s;
    }
    __syncwarp();

    ull acc0[8], acc1[8];
    #pragma unroll
    for (int r = 0; r < 8; ++r) { acc0[r] = 0ULL; acc1[r] = 0ULL; }
    #pragma unroll 4
    for (int k = 0; k < 128; k += 4) {
        ulonglong2 wk0 = *(const ulonglong2*)(ws + (k + 0) * 128 + col);
        ulonglong2 wk1 = *(const ulonglong2*)(ws + (k + 1) * 128 + col);
        ulonglong2 wk2 = *(const ulonglong2*)(ws + (k + 2) * 128 + col);
        ulonglong2 wk3 = *(const ulonglong2*)(ws + (k + 3) * 128 + col);
        #pragma unroll
        for (int r = 0; r < 8; ++r) {
            float4 av = *(const float4*)(act + (m0 + r) * 128 + k);
            ull p0 = pack2(av.x), p1 = pack2(av.y), p2 = pack2(av.z), p3 = pack2(av.w);
            fma2(acc0[r], p0, wk0.x); fma2(acc1[r], p0, wk0.y);
            fma2(acc0[r], p1, wk1.x); fma2(acc1[r], p1, wk1.y);
            fma2(acc0[r], p2, wk2.x); fma2(acc1[r], p2, wk2.y);
            fma2(acc0[r], p3, wk3.x); fma2(acc1[r], p3, wk3.y);
        }
    }
    #pragma unroll
    for (int r = 0; r < 8; ++r) {
        float2 lo = unpk(acc0[r]);
        float2 hi = unpk(acc1[r]);
        float4 v;
        v.x = lk(lo.x + bias.x);
        v.y = lk(lo.y + bias.y);
        v.z = lk(hi.x + bias.z);
        v.w = lk(hi.y + bias.w);
        *(float4*)(g_q + (b * 64 + m0 + r) * 128 + col) = v;
    }
}

// =====================================================================
// Kernel 7: out = leaky(q @ w5 + b5) * mask
// =====================================================================
__global__ __launch_bounds__(256, 1) void outb_kernel(const float* __restrict__ mask,
                                                      const float* __restrict__ w5,
                                                      const float* __restrict__ b5,
                                                      float* __restrict__ out) {
    extern __shared__ float sm[];
    float* ws  = sm;            // 128 x 128 slice of w5
    float* act = sm + 16384;    // 64 x 128
    const int t = threadIdx.x, b = blockIdx.x;
    const int n0 = blockIdx.y * 128;

    for (int i = t; i < 4096; i += 256) {
        int k = i >> 5, nq = i & 31;
        ((float4*)ws)[k * 32 + nq] = ((const float4*)(w5 + k * 512 + n0))[nq];
    }
    __syncthreads();

    const int wid = t >> 5, lane = t & 31;
    const int m0 = wid * 8, col = lane * 4;
    float4 bias = *(const float4*)(b5 + n0 + col);

    #pragma unroll
    for (int r = 0; r < 8; ++r) {
        int row = b * 64 + m0 + r;
        *(float4*)(act + (m0 + r) * 128 + col) = *(const float4*)(g_q + row * 128 + col);
    }
    __syncwarp();

    ull acc0[8], acc1[8];
    #pragma unroll
    for (int r = 0; r < 8; ++r) { acc0[r] = 0ULL; acc1[r] = 0ULL; }
    #pragma unroll 4
    for (int k = 0; k < 128; k += 4) {
        ulonglong2 wk0 = *(const ulonglong2*)(ws + (k + 0) * 128 + col);
        ulonglong2 wk1 = *(const ulonglong2*)(ws + (k + 1) * 128 + col);
        ulonglong2 wk2 = *(const ulonglong2*)(ws + (k + 2) * 128 + col);
        ulonglong2 wk3 = *(const ulonglong2*)(ws + (k + 3) * 128 + col);
        #pragma unroll
        for (int r = 0; r < 8; ++r) {
            float4 av = *(const float4*)(act + (m0 + r) * 128 + k);
            ull p0 = pack2(av.x), p1 = pack2(av.y), p2 = pack2(av.z), p3 = pack2(av.w);
            fma2(acc0[r], p0, wk0.x); fma2(acc1[r], p0, wk0.y);
            fma2(acc0[r], p1, wk1.x); fma2(acc1[r], p1, wk1.y);
            fma2(acc0[r], p2, wk2.x); fma2(acc1[r], p2, wk2.y);
            fma2(acc0[r], p3, wk3.x); fma2(acc1[r], p3, wk3.y);
        }
    }
    #pragma unroll
    for (int r = 0; r < 8; ++r) {
        int i = m0 + r;
        float mk = mask[i * 32 + b];
        float2 lo = unpk(acc0[r]);
        float2 hi = unpk(acc1[r]);
        float4 v;
        v.x = lk(lo.x + bias.x) * mk;
        v.y = lk(lo.y + bias.y) * mk;
        v.z = lk(hi.x + bias.z) * mk;
        v.w = lk(hi.y + bias.w) * mk;
        *(float4*)(out + (i * 32 + b) * 512 + n0 + col) = v;
    }
}

// =====================================================================
extern "C" void kernel_launch(void* const* d_in, const int* in_sizes, int n_in,
                              void* d_out, int out_size) {
    const float* x     = (const float*)d_in[0];
    const float* xmask = (const float*)d_in[1];
    const float* cw0   = (const float*)d_in[2];
    const float* cb0   = (const float*)d_in[3];
    const float* gam0  = (const float*)d_in[4];
    const float* bet0  = (const float*)d_in[5];
    const float* cw1   = (const float*)d_in[6];
    const float* cb1   = (const float*)d_in[7];
    const float* gam1  = (const float*)d_in[8];
    const float* bet1  = (const float*)d_in[9];
    const float* w0    = (const float*)d_in[10];
    const float* b0    = (const float*)d_in[11];
    const float* w1    = (const float*)d_in[12];
    const float* b1    = (const float*)d_in[13];
    const float* w2    = (const float*)d_in[14];
    const float* b2    = (const float*)d_in[15];
    const float* w3    = (const float*)d_in[16];
    const float* b3    = (const float*)d_in[17];
    const float* w4    = (const float*)d_in[18];
    const float* b4    = (const float*)d_in[19];
    const float* w5    = (const float*)d_in[20];
    const float* b5    = (const float*)d_in[21];
    float* out = (float*)d_out;

    cudaFuncSetAttribute(pair_kernel, cudaFuncAttributeMaxDynamicSharedMemorySize, 172160);
    cudaFuncSetAttribute(qa_kernel,   cudaFuncAttributeMaxDynamicSharedMemorySize, 98304);
    cudaFuncSetAttribute(outb_kernel, cudaFuncAttributeMaxDynamicSharedMemorySize, 98304);

    convs_kernel<<<384, 256>>>(x, xmask, cw0, cb0, cw1, cb1);
    stats_kernel<<<384, 256>>>();
    bn_kernel<<<(2048 * 384 + 255) / 256, 256>>>(xmask, gam0, bet0, gam1, bet1);
    ab_kernel<<<dim3(32, 4, 2), 256>>>(w0, b0);
    pair_kernel<<<dim3(32, 4), 256, 172160>>>(w1, b1, w2, b2, w3, b3);
    qa_kernel<<<32, 256, 98304>>>(xmask, w4, b4);
    outb_kernel<<<dim3(32, 4), 256, 98304>>>(xmask, w5, b5, out);
}

// round 17
// speedup vs baseline: 2.7049x; 1.3546x over previous
#include <cuda_runtime.h>
#include <cstdint>

typedef unsigned long long ull;

// ---------------- static device scratch (no allocations allowed) ----------------
__device__ float g_y[2048 * 384];           // conv outputs + bias, rows r = l*32+b
__device__ float g_h[2048 * 384];           // post-BN/leaky/mask features
__device__ float g_mean[384];
__device__ float g_rstd[384];
__device__ float g_a[32 * 64 * 128];        // (b,l,128): h @ w0[:C] + b0
__device__ float g_bb[32 * 64 * 128];       // (b,l,128): h @ w0[C:]
__device__ float g_pacc[4 * 2048 * 128];    // per j-chunk partial sums
__device__ float g_q[2048 * 128];           // output-MLP hidden

__device__ __forceinline__ float lk(float x) { return x >= 0.f ? x : 0.1f * x; }

__device__ __forceinline__ void fma2(ull& acc, ull a, ull b) {
    asm("fma.rn.f32x2 %0,%1,%2,%0;" : "+l"(acc) : "l"(a), "l"(b));
}
__device__ __forceinline__ ull pack2(float x) {
    ull r; asm("mov.b64 %0,{%1,%1};" : "=l"(r) : "f"(x)); return r;
}
__device__ __forceinline__ float2 unpk(ull v) {
    float2 f; asm("mov.b64 {%0,%1},%2;" : "=f"(f.x), "=f"(f.y) : "l"(v)); return f;
}
// pack two fp32 -> f16x2 word, lo = first arg
__device__ __forceinline__ uint32_t pkh(float lo, float hi) {
    uint32_t r; asm("cvt.rn.f16x2.f32 %0, %1, %2;" : "=r"(r) : "f"(hi), "f"(lo)); return r;
}
// m16n8k16 fp16 MMA, fp32 accumulate
__device__ __forceinline__ void mma16(float* d,
                                      uint32_t a0, uint32_t a1, uint32_t a2, uint32_t a3,
                                      uint32_t b0, uint32_t b1) {
    asm("mma.sync.aligned.m16n8k16.row.col.f32.f16.f16.f32 "
        "{%0,%1,%2,%3}, {%4,%5,%6,%7}, {%8,%9}, {%0,%1,%2,%3};"
        : "+f"(d[0]), "+f"(d[1]), "+f"(d[2]), "+f"(d[3])
        : "r"(a0), "r"(a1), "r"(a2), "r"(a3), "r"(b0), "r"(b1));
}
// swizzled word position within a row for k-pair kp (payload 16 words)
__device__ __forceinline__ int posw(int kp) {
    int jj = kp & 7;
    return ((kp >> 3) << 3) + ((jj & 3) << 1) + (jj >> 2);
}

// =====================================================================
// Kernel 1: both convolutions as fp16-MMA shifted GEMMs (merged grid)
// block tile 64m x 64n, 8 warps (2m x 4n), K-chunk 32.
// bx<128: conv0 (K=512, N=256, 4 n-tiles); else conv1 (K=1536, N=128, 2 n-tiles)
// =====================================================================
__global__ __launch_bounds__(256) void convs_h_kernel(const float* __restrict__ x,
                                                      const float* __restrict__ mask,
                                                      const float* __restrict__ cw0,
                                                      const float* __restrict__ cb0,
                                                      const float* __restrict__ cw1,
                                                      const float* __restrict__ cb1) {
    __shared__ uint32_t A_s[64 * 20];
    __shared__ uint32_t B_s[64 * 20];
    const int bx = blockIdx.x;
    const float* w; const float* cb; int bm0, bn0, coff, K, PAD;
    if (bx < 128) { w = cw0; cb = cb0; bm0 = (bx >> 2) * 64; bn0 = (bx & 3) * 64; coff = 0;   K = 512;  PAD = 0; }
    else { int b2 = bx - 128; w = cw1; cb = cb1; bm0 = (b2 >> 1) * 64; bn0 = (b2 & 1) * 64; coff = 256; K = 1536; PAD = 1; }

    const int t = threadIdx.x, lane = t & 31, wid = t >> 5;
    const int g = lane >> 2, tig = lane & 3;
    const int mb = (wid >> 2) * 32, nb = (wid & 3) * 16;

    float D[4][4];
    #pragma unroll
    for (int q = 0; q < 4; ++q)
        #pragma unroll
        for (int e = 0; e < 4; ++e) D[q][e] = 0.f;

    for (int k0 = 0; k0 < K; k0 += 32) {
        #pragma unroll
        for (int it = 0; it < 4; ++it) {
            int idx = t + it * 256;           // 0..1023
            int mm = idx >> 4, kp = idx & 15;
            int r = bm0 + mm, l = r >> 5, bq = r & 31;
            int kidx = k0 + 2 * kp;
            int lp = l + (kidx >> 9) - PAD;
            uint32_t wv = 0;
            if (lp >= 0 && lp < 64) {
                int rb = lp * 32 + bq;
                float2 xv = *(const float2*)(x + rb * 512 + (kidx & 511));
                float mk = mask[rb];
                wv = pkh(xv.x * mk, xv.y * mk);
            }
            A_s[mm * 20 + posw(kp)] = wv;
        }
        #pragma unroll
        for (int it = 0; it < 4; ++it) {
            int idx = t + it * 256;
            int n = idx >> 4, kp = idx & 15;
            float2 wv2 = *(const float2*)(w + (bn0 + n) * K + k0 + 2 * kp);
            B_s[n * 20 + posw(kp)] = pkh(wv2.x, wv2.y);
        }
        __syncthreads();
        #pragma unroll
        for (int kc = 0; kc < 2; ++kc) {
            int ko = kc * 8 + tig * 2;
            uint2 aA = *(const uint2*)(A_s + (mb + g) * 20 + ko);
            uint2 aB = *(const uint2*)(A_s + (mb + g + 8) * 20 + ko);
            uint2 aC = *(const uint2*)(A_s + (mb + g + 16) * 20 + ko);
            uint2 aD = *(const uint2*)(A_s + (mb + g + 24) * 20 + ko);
            #pragma unroll
            for (int nt = 0; nt < 2; ++nt) {
                uint2 bw = *(const uint2*)(B_s + (nb + nt * 8 + g) * 20 + ko);
                mma16(D[nt],     aA.x, aB.x, aA.y, aB.y, bw.x, bw.y);
                mma16(D[2 + nt], aC.x, aD.x, aC.y, aD.y, bw.x, bw.y);
            }
        }
        __syncthreads();
    }
    #pragma unroll
    for (int mt = 0; mt < 2; ++mt)
        #pragma unroll
        for (int nt = 0; nt < 2; ++nt) {
            float* f = D[mt * 2 + nt];
            int c = bn0 + nb + nt * 8 + 2 * tig;
            float blo = cb[c], bhi = cb[c + 1];
            int r0 = bm0 + mb + mt * 16 + g;
            g_y[r0 * 384 + coff + c]           = f[0] + blo;
            g_y[r0 * 384 + coff + c + 1]       = f[1] + bhi;
            g_y[(r0 + 8) * 384 + coff + c]     = f[2] + blo;
            g_y[(r0 + 8) * 384 + coff + c + 1] = f[3] + bhi;
        }
}

// =====================================================================
// Kernel 2: per-channel batch stats
// =====================================================================
__global__ __launch_bounds__(256) void stats_kernel() {
    const int c = blockIdx.x;
    const int t = threadIdx.x;
    float s = 0.f, s2 = 0.f;
    for (int r = t; r < 2048; r += 256) {
        float v = g_y[r * 384 + c];
        s += v; s2 += v * v;
    }
    __shared__ float ss[256], ss2[256];
    ss[t] = s; ss2[t] = s2;
    __syncthreads();
    for (int off = 128; off > 0; off >>= 1) {
        if (t < off) { ss[t] += ss[t + off]; ss2[t] += ss2[t + off]; }
        __syncthreads();
    }
    if (t == 0) {
        float m = ss[0] * (1.f / 2048.f);
        float var = ss2[0] * (1.f / 2048.f) - m * m;
        g_mean[c] = m;
        g_rstd[c] = rsqrtf(var + 1e-5f);
    }
}

// =====================================================================
// Kernel 3: BN apply + leaky + mask -> h
// =====================================================================
__global__ __launch_bounds__(256) void bn_kernel(const float* __restrict__ mask,
                                                 const float* __restrict__ gamma0,
                                                 const float* __restrict__ beta0,
                                                 const float* __restrict__ gamma1,
                                                 const float* __restrict__ beta1) {
    int idx = blockIdx.x * 256 + threadIdx.x;
    if (idx >= 2048 * 384) return;
    int r = idx / 384, c = idx - r * 384;
    float g  = (c < 256) ? gamma0[c] : gamma1[c - 256];
    float bt = (c < 256) ? beta0[c]  : beta1[c - 256];
    float v = (g_y[idx] - g_mean[c]) * g_rstd[c] * g + bt;
    g_h[idx] = lk(v) * mask[r];
}

// =====================================================================
// Kernel 4: a/bb via fp16 MMA (K=384), grid (32 mtiles, 2 ntiles, 2 which)
// =====================================================================
__global__ __launch_bounds__(256) void ab_h_kernel(const float* __restrict__ w0,
                                                   const float* __restrict__ b0) {
    __shared__ uint32_t A_s[64 * 20];
    __shared__ uint32_t B_s[64 * 20];
    const int bm0 = blockIdx.x * 64;
    const int bn0 = blockIdx.y * 64;
    const int which = blockIdx.z;
    const int wb = which * 384;

    const int t = threadIdx.x, lane = t & 31, wid = t >> 5;
    const int g = lane >> 2, tig = lane & 3;
    const int mb = (wid >> 2) * 32, nb = (wid & 3) * 16;

    float D[4][4];
    #pragma unroll
    for (int q = 0; q < 4; ++q)
        #pragma unroll
        for (int e = 0; e < 4; ++e) D[q][e] = 0.f;

    for (int k0 = 0; k0 < 384; k0 += 32) {
        #pragma unroll
        for (int it = 0; it < 4; ++it) {
            int idx = t + it * 256;
            int mm = idx >> 4, kp = idx & 15;
            float2 hv = *(const float2*)(g_h + (bm0 + mm) * 384 + k0 + 2 * kp);
            A_s[mm * 20 + posw(kp)] = pkh(hv.x, hv.y);
        }
        #pragma unroll
        for (int it = 0; it < 4; ++it) {
            int idx = t + it * 256;
            int n = idx & 63, kp = idx >> 6;     // kp 0..15
            float lo = w0[(wb + k0 + 2 * kp) * 128 + bn0 + n];
            float hi = w0[(wb + k0 + 2 * kp + 1) * 128 + bn0 + n];
            B_s[n * 20 + posw(kp)] = pkh(lo, hi);
        }
        __syncthreads();
        #pragma unroll
        for (int kc = 0; kc < 2; ++kc) {
            int ko = kc * 8 + tig * 2;
            uint2 aA = *(const uint2*)(A_s + (mb + g) * 20 + ko);
            uint2 aB = *(const uint2*)(A_s + (mb + g + 8) * 20 + ko);
            uint2 aC = *(const uint2*)(A_s + (mb + g + 16) * 20 + ko);
            uint2 aD = *(const uint2*)(A_s + (mb + g + 24) * 20 + ko);
            #pragma unroll
            for (int nt = 0; nt < 2; ++nt) {
                uint2 bw = *(const uint2*)(B_s + (nb + nt * 8 + g) * 20 + ko);
                mma16(D[nt],     aA.x, aB.x, aA.y, aB.y, bw.x, bw.y);
                mma16(D[2 + nt], aC.x, aD.x, aC.y, aD.y, bw.x, bw.y);
            }
        }
        __syncthreads();
    }
    float* dst = which ? g_bb : g_a;
    #pragma unroll
    for (int mt = 0; mt < 2; ++mt)
        #pragma unroll
        for (int nt = 0; nt < 2; ++nt) {
            float* f = D[mt * 2 + nt];
            int c = bn0 + nb + nt * 8 + 2 * tig;
            float blo = 0.f, bhi = 0.f;
            if (which == 0) { blo = b0[c]; bhi = b0[c + 1]; }
            int r0 = bm0 + mb + mt * 16 + g;
            int r1 = r0 + 8;
            dst[((r0 & 31) * 64 + (r0 >> 5)) * 128 + c]     = f[0] + blo;
            dst[((r0 & 31) * 64 + (r0 >> 5)) * 128 + c + 1] = f[1] + bhi;
            dst[((r1 & 31) * 64 + (r1 >> 5)) * 128 + c]     = f[2] + blo;
            dst[((r1 & 31) * 64 + (r1 >> 5)) * 128 + c + 1] = f[3] + bhi;
        }
}

// =====================================================================
// Kernel 5: fused pairwise MLP, fp16 mma.sync.m16n8k16 (fp32 accumulate)
// grid (32 b, 4 jc), 256 threads = 8 warps in 2 row-bands x 4 col-bands.
// Double-buffered act (fill/L1 -> buf0, L0 epi -> buf1, L1 epi -> buf0):
// 4 block syncs per j instead of 6.
// SMEM floats/words: ws 27648 | a_s 8320 | bb_s 2080 | bias 384 |
//                    act0 4608 | act1 4608  -> 190592 B
// =====================================================================
__global__ __launch_bounds__(256, 1) void pair_kernel(const float* __restrict__ w1,
                                                      const float* __restrict__ b1,
                                                      const float* __restrict__ w2,
                                                      const float* __restrict__ b2,
                                                      const float* __restrict__ w3,
                                                      const float* __restrict__ b3) {
    extern __shared__ float sm[];
    uint32_t* ws    = (uint32_t*)sm;            // 27648 words
    float*    a_s   = sm + 27648;               // 8320
    float*    bb_s  = sm + 35968;               // 2080
    float*    bias_s= sm + 38048;               // 384
    uint32_t* act0  = (uint32_t*)(sm + 38432);  // 4608
    uint32_t* act1  = (uint32_t*)(sm + 43040);  // 4608

    const int t = threadIdx.x;
    const int b = blockIdx.x, jc = blockIdx.y;

    // ---- stage weights as f16x2, swizzled [n][pos(kp)], row stride 72 ----
    for (int idx = t; idx < 8192; idx += 256) {
        int n = idx & 127, kp = idx >> 7;
        int jj = kp & 7;
        int pos = n * 72 + ((kp >> 3) << 3) + ((jj & 3) << 1) + (jj >> 2);
        int s0 = (2 * kp) * 128 + n, s1 = s0 + 128;
        ws[pos]          = pkh(w1[s0], w1[s1]);
        ws[9216 + pos]   = pkh(w2[s0], w2[s1]);
        ws[18432 + pos]  = pkh(w3[s0], w3[s1]);
    }
    for (int idx = t; idx < 8192; idx += 256) {
        int i = idx >> 7, k = idx & 127;
        a_s[i * 130 + k] = g_a[(b * 64 + i) * 128 + k];
    }
    for (int idx = t; idx < 2048; idx += 256) {
        int jj = idx >> 7, k = idx & 127;
        bb_s[jj * 130 + k] = g_bb[(b * 64 + jc * 16 + jj) * 128 + k];
    }
    if (t < 128) {
        bias_s[t]       = b1[t];
        bias_s[128 + t] = b2[t];
        bias_s[256 + t] = b3[t];
    }
    __syncthreads();

    const int lane = t & 31, wid = t >> 5;
    const int g = lane >> 2, tig = lane & 3;
    const int mb = (wid >> 2) << 5;
    const int nb = (wid & 3) << 5;

    const int kp_f = t & 63, ih = t >> 6;
    const int jjf = kp_f & 7;
    const int pos_f = ((kp_f >> 3) << 3) + ((jjf & 3) << 1) + (jjf >> 2);

    int epos[4];
    #pragma unroll
    for (int nt = 0; nt < 4; ++nt) {
        int kp = (nb >> 1) + nt * 4 + tig;
        int jj = kp & 7;
        epos[nt] = ((kp >> 3) << 3) + ((jj & 3) << 1) + (jj >> 2);
    }

    float jacc[8][4];
    #pragma unroll
    for (int q = 0; q < 8; ++q)
        #pragma unroll
        for (int e = 0; e < 4; ++e) jacc[q][e] = 0.f;

    for (int jj16 = 0; jj16 < 16; ++jj16) {
        // ---- fill act0 = f16(leaky(a + bb)) ----
        {
            float2 bv = *(const float2*)(bb_s + jj16 * 130 + 2 * kp_f);
            #pragma unroll
            for (int q = 0; q < 16; ++q) {
                int i = ih * 16 + q;
                float2 av = *(const float2*)(a_s + i * 130 + 2 * kp_f);
                act0[i * 72 + pos_f] = pkh(lk(av.x + bv.x), lk(av.y + bv.y));
            }
        }
        __syncthreads();

        #pragma unroll
        for (int L = 0; L < 3; ++L) {
            const uint32_t* wl = ws + L * 9216;
            const uint32_t* rd = (L == 1) ? act1 : act0;
            uint32_t*       wr = (L == 0) ? act1 : act0;

            float D[8][4];
            #pragma unroll
            for (int q = 0; q < 8; ++q)
                #pragma unroll
                for (int e = 0; e < 4; ++e) D[q][e] = 0.f;

            #pragma unroll
            for (int s = 0; s < 8; ++s) {
                const int ko = s * 8 + tig * 2;
                uint2 aA = *(const uint2*)(rd + (mb + g) * 72 + ko);
                uint2 aB = *(const uint2*)(rd + (mb + g + 8) * 72 + ko);
                uint2 aC = *(const uint2*)(rd + (mb + g + 16) * 72 + ko);
                uint2 aD = *(const uint2*)(rd + (mb + g + 24) * 72 + ko);
                #pragma unroll
                for (int nt = 0; nt < 4; ++nt) {
                    uint2 bw = *(const uint2*)(wl + (nb + nt * 8 + g) * 72 + ko);
                    mma16(D[nt],     aA.x, aB.x, aA.y, aB.y, bw.x, bw.y);
                    mma16(D[4 + nt], aC.x, aD.x, aC.y, aD.y, bw.x, bw.y);
                }
            }

            if (L < 2) {
                #pragma unroll
                for (int mt = 0; mt < 2; ++mt) {
                    #pragma unroll
                    for (int nt = 0; nt < 4; ++nt) {
                        float* f = D[mt * 4 + nt];
                        int c0 = nb + nt * 8 + 2 * tig;
                        float2 bi = *(const float2*)(bias_s + L * 128 + c0);
                        int r0 = (mb + mt * 16 + g) * 72;
                        wr[r0 + epos[nt]]          = pkh(lk(f[0] + bi.x), lk(f[1] + bi.y));
                        wr[r0 + 8 * 72 + epos[nt]] = pkh(lk(f[2] + bi.x), lk(f[3] + bi.y));
                    }
                }
                __syncthreads();   // writes visible before next layer reads
            } else {
                #pragma unroll
                for (int mt = 0; mt < 2; ++mt)
                    #pragma unroll
                    for (int nt = 0; nt < 4; ++nt) {
                        float* f = D[mt * 4 + nt];
                        int c0 = nb + nt * 8 + 2 * tig;
                        float2 bi = *(const float2*)(bias_s + 256 + c0);
                        float* ja = jacc[mt * 4 + nt];
                        ja[0] += lk(f[0] + bi.x);
                        ja[1] += lk(f[1] + bi.y);
                        ja[2] += lk(f[2] + bi.x);
                        ja[3] += lk(f[3] + bi.y);
                    }
                __syncthreads();   // L2 reads of act0 done before next fill
            }
        }
    }

    #pragma unroll
    for (int mt = 0; mt < 2; ++mt)
        #pragma unroll
        for (int nt = 0; nt < 4; ++nt) {
            float* f = jacc[mt * 4 + nt];
            int c0 = nb + nt * 8 + 2 * tig;
            int r0 = jc * 2048 + b * 64 + mb + mt * 16 + g;
            *(float2*)(g_pacc + r0 * 128 + c0)       = make_float2(f[0], f[1]);
            *(float2*)(g_pacc + (r0 + 8) * 128 + c0) = make_float2(f[2], f[3]);
        }
}

// =====================================================================
// Kernel 6: q = leaky( (mean_j p * mask_i) @ w4 + b4 )
// =====================================================================
__global__ __launch_bounds__(256, 1) void qa_kernel(const float* __restrict__ mask,
                                                    const float* __restrict__ w4,
                                                    const float* __restrict__ b4) {
    extern __shared__ float sm[];
    float* ws  = sm;            // 128 x 128
    float* act = sm + 16384;    // 64 x 128
    const int t = threadIdx.x, b = blockIdx.x;

    for (int i = t; i < 4096; i += 256) ((float4*)ws)[i] = ((const float4*)w4)[i];
    __syncthreads();

    const int wid = t >> 5, lane = t & 31;
    const int m0 = wid * 8, col = lane * 4;
    float4 bias = *(const float4*)(b4 + col);

    #pragma unroll
    for (int r = 0; r < 8; ++r) {
        int i = m0 + r;
        int row = b * 64 + i;
        float mk = mask[i * 32 + b] * (1.f / 64.f);
        float4 s = make_float4(0.f, 0.f, 0.f, 0.f);
        #pragma unroll
        for (int cp = 0; cp < 4; ++cp) {
            float4 p = *(const float4*)(g_pacc + (cp * 2048 + row) * 128 + col);
            s.x += p.x; s.y += p.y; s.z += p.z; s.w += p.w;
        }
        s.x *= mk; s.y *= mk; s.z *= mk; s.w *= mk;
        *(float4*)(act + i * 128 + col) = s;
    }
    __syncwarp();

    ull acc0[8], acc1[8];
    #pragma unroll
    for (int r = 0; r < 8; ++r) { acc0[r] = 0ULL; acc1[r] = 0ULL; }
    #pragma unroll 4
    for (int k = 0; k < 128; k += 4) {
        ulonglong2 wk0 = *(const ulonglong2*)(ws + (k + 0) * 128 + col);
        ulonglong2 wk1 = *(const ulonglong2*)(ws + (k + 1) * 128 + col);
        ulonglong2 wk2 = *(const ulonglong2*)(ws + (k + 2) * 128 + col);
        ulonglong2 wk3 = *(const ulonglong2*)(ws + (k + 3) * 128 + col);
        #pragma unroll
        for (int r = 0; r < 8; ++r) {
            float4 av = *(const float4*)(act + (m0 + r) * 128 + k);
            ull p0 = pack2(av.x), p1 = pack2(av.y), p2 = pack2(av.z), p3 = pack2(av.w);
            fma2(acc0[r], p0, wk0.x); fma2(acc1[r], p0, wk0.y);
            fma2(acc0[r], p1, wk1.x); fma2(acc1[r], p1, wk1.y);
            fma2(acc0[r], p2, wk2.x); fma2(acc1[r], p2, wk2.y);
            fma2(acc0[r], p3, wk3.x); fma2(acc1[r], p3, wk3.y);
        }
    }
    #pragma unroll
    for (int r = 0; r < 8; ++r) {
        float2 lo = unpk(acc0[r]);
        float2 hi = unpk(acc1[r]);
        float4 v;
        v.x = lk(lo.x + bias.x);
        v.y = lk(lo.y + bias.y);
        v.z = lk(hi.x + bias.z);
        v.w = lk(hi.y + bias.w);
        *(float4*)(g_q + (b * 64 + m0 + r) * 128 + col) = v;
    }
}

// =====================================================================
// Kernel 7: out = leaky(q @ w5 + b5) * mask
// =====================================================================
__global__ __launch_bounds__(256, 1) void outb_kernel(const float* __restrict__ mask,
                                                      const float* __restrict__ w5,
                                                      const float* __restrict__ b5,
                                                      float* __restrict__ out) {
    extern __shared__ float sm[];
    float* ws  = sm;            // 128 x 128 slice of w5
    float* act = sm + 16384;    // 64 x 128
    const int t = threadIdx.x, b = blockIdx.x;
    const int n0 = blockIdx.y * 128;

    for (int i = t; i < 4096; i += 256) {
        int k = i >> 5, nq = i & 31;
        ((float4*)ws)[k * 32 + nq] = ((const float4*)(w5 + k * 512 + n0))[nq];
    }
    __syncthreads();

    const int wid = t >> 5, lane = t & 31;
    const int m0 = wid * 8, col = lane * 4;
    float4 bias = *(const float4*)(b5 + n0 + col);

    #pragma unroll
    for (int r = 0; r < 8; ++r) {
        int row = b * 64 + m0 + r;
        *(float4*)(act + (m0 + r) * 128 + col) = *(const float4*)(g_q + row * 128 + col);
    }
    __syncwarp();

    ull acc0[8], acc1[8];
    #pragma unroll
    for (int r = 0; r < 8; ++r) { acc0[r] = 0ULL; acc1[r] = 0ULL; }
    #pragma unroll 4
    for (int k = 0; k < 128; k += 4) {
        ulonglong2 wk0 = *(const ulonglong2*)(ws + (k + 0) * 128 + col);
        ulonglong2 wk1 = *(const ulonglong2*)(ws + (k + 1) * 128 + col);
        ulonglong2 wk2 = *(const ulonglong2*)(ws + (k + 2) * 128 + col);
        ulonglong2 wk3 = *(const ulonglong2*)(ws + (k + 3) * 128 + col);
        #pragma unroll
        for (int r = 0; r < 8; ++r) {
            float4 av = *(const float4*)(act + (m0 + r) * 128 + k);
            ull p0 = pack2(av.x), p1 = pack2(av.y), p2 = pack2(av.z), p3 = pack2(av.w);
            fma2(acc0[r], p0, wk0.x); fma2(acc1[r], p0, wk0.y);
            fma2(acc0[r], p1, wk1.x); fma2(acc1[r], p1, wk1.y);
            fma2(acc0[r], p2, wk2.x); fma2(acc1[r], p2, wk2.y);
            fma2(acc0[r], p3, wk3.x); fma2(acc1[r], p3, wk3.y);
        }
    }
    #pragma unroll
    for (int r = 0; r < 8; ++r) {
        int i = m0 + r;
        float mk = mask[i * 32 + b];
        float2 lo = unpk(acc0[r]);
        float2 hi = unpk(acc1[r]);
        float4 v;
        v.x = lk(lo.x + bias.x) * mk;
        v.y = lk(lo.y + bias.y) * mk;
        v.z = lk(hi.x + bias.z) * mk;
        v.w = lk(hi.y + bias.w) * mk;
        *(float4*)(out + (i * 32 + b) * 512 + n0 + col) = v;
    }
}

// =====================================================================
extern "C" void kernel_launch(void* const* d_in, const int* in_sizes, int n_in,
                              void* d_out, int out_size) {
    const float* x     = (const float*)d_in[0];
    const float* xmask = (const float*)d_in[1];
    const float* cw0   = (const float*)d_in[2];
    const float* cb0   = (const float*)d_in[3];
    const float* gam0  = (const float*)d_in[4];
    const float* bet0  = (const float*)d_in[5];
    const float* cw1   = (const float*)d_in[6];
    const float* cb1   = (const float*)d_in[7];
    const float* gam1  = (const float*)d_in[8];
    const float* bet1  = (const float*)d_in[9];
    const float* w0    = (const float*)d_in[10];
    const float* b0    = (const float*)d_in[11];
    const float* w1    = (const float*)d_in[12];
    const float* b1    = (const float*)d_in[13];
    const float* w2    = (const float*)d_in[14];
    const float* b2    = (const float*)d_in[15];
    const float* w3    = (const float*)d_in[16];
    const float* b3    = (const float*)d_in[17];
    const float* w4    = (const float*)d_in[18];
    const float* b4    = (const float*)d_in[19];
    const float* w5    = (const float*)d_in[20];
    const float* b5    = (const float*)d_in[21];
    float* out = (float*)d_out;

    cudaFuncSetAttribute(pair_kernel, cudaFuncAttributeMaxDynamicSharedMemorySize, 190592);
    cudaFuncSetAttribute(qa_kernel,   cudaFuncAttributeMaxDynamicSharedMemorySize, 98304);
    cudaFuncSetAttribute(outb_kernel, cudaFuncAttributeMaxDynamicSharedMemorySize, 98304);

    convs_h_kernel<<<192, 256>>>(x, xmask, cw0, cb0, cw1, cb1);
    stats_kernel<<<384, 256>>>();
    bn_kernel<<<(2048 * 384 + 255) / 256, 256>>>(xmask, gam0, bet0, gam1, bet1);
    ab_h_kernel<<<dim3(32, 2, 2), 256>>>(w0, b0);
    pair_kernel<<<dim3(32, 4), 256, 190592>>>(w1, b1, w2, b2, w3, b3);
    qa_kernel<<<32, 256, 98304>>>(xmask, w4, b4);
    outb_kernel<<<dim3(32, 4), 256, 98304>>>(xmask, w5, b5, out);
}